// round 1
// baseline (speedup 1.0000x reference)
#include <cuda_runtime.h>

#define M_ROWS 8192
#define N_CODES 8192
#define K_DIM 256

#define BM 128
#define BN 128
#define BK 16
#define TM 8
#define TN 8
#define NSPLIT 4
#define NT_PER (N_CODES / NSPLIT)

__device__ float g_esq[N_CODES];
__device__ unsigned long long g_best[M_ROWS];

__device__ __forceinline__ unsigned long long pack_key(float v, unsigned int idx) {
    unsigned int u = __float_as_uint(v);
    u = (u & 0x80000000u) ? ~u : (u | 0x80000000u);   // order-preserving float->uint
    return ((unsigned long long)u << 32) | (unsigned long long)idx;
}

// Prologue: e_sq per code (one warp per code) + reset g_best.
__global__ void vq_init_kernel(const float* __restrict__ embed) {
    int gtid = blockIdx.x * blockDim.x + threadIdx.x;
    int warp = gtid >> 5;
    int lane = gtid & 31;
    if (warp < N_CODES) {
        const float* e = embed + (size_t)warp * K_DIM;
        float s = 0.f;
        #pragma unroll
        for (int k = lane * 4; k < K_DIM; k += 128) {
            float4 v = *(const float4*)(e + k);
            s += v.x * v.x + v.y * v.y + v.z * v.z + v.w * v.w;
        }
        #pragma unroll
        for (int o = 16; o > 0; o >>= 1) s += __shfl_xor_sync(0xffffffffu, s, o);
        if (lane == 0) g_esq[warp] = s;
    }
    if (gtid < M_ROWS) g_best[gtid] = 0xFFFFFFFFFFFFFFFFull;
}

// Fused GEMM + argmin. Each block: BM rows x NT_PER codes.
__global__ __launch_bounds__(256, 2)
void vq_argmin_kernel(const float* __restrict__ x, const float* __restrict__ embed) {
    __shared__ float As[2][BK][BM];
    __shared__ float Bs[2][BK][BN];
    __shared__ unsigned long long red[16][BM];

    const int m0 = blockIdx.x * BM;
    const int n_begin = blockIdx.y * NT_PER;

    const int tid = threadIdx.x;
    const int tx = tid & 15;
    const int ty = tid >> 4;

    const int lr = tid >> 1;          // load row 0..127
    const int lc = (tid & 1) * 8;     // k offset 0 or 8

    const float* xp = x + (size_t)(m0 + lr) * K_DIM + lc;

    float bestv[TM];
    unsigned int besti[TM];
    #pragma unroll
    for (int i = 0; i < TM; i++) { bestv[i] = 3.4e38f; besti[i] = 0u; }

    for (int nt0 = 0; nt0 < NT_PER; nt0 += BN) {
        const int nbase = n_begin + nt0;
        const float* ep = embed + (size_t)(nbase + lr) * K_DIM + lc;

        float acc[TM][TN];
        #pragma unroll
        for (int i = 0; i < TM; i++)
            #pragma unroll
            for (int j = 0; j < TN; j++) acc[i][j] = 0.f;

        // prefetch k-tile 0 into registers, store to buffer 0
        float4 ra0 = *(const float4*)(xp + 0);
        float4 ra1 = *(const float4*)(xp + 4);
        float4 rb0 = *(const float4*)(ep + 0);
        float4 rb1 = *(const float4*)(ep + 4);

        As[0][lc + 0][lr] = ra0.x; As[0][lc + 1][lr] = ra0.y;
        As[0][lc + 2][lr] = ra0.z; As[0][lc + 3][lr] = ra0.w;
        As[0][lc + 4][lr] = ra1.x; As[0][lc + 5][lr] = ra1.y;
        As[0][lc + 6][lr] = ra1.z; As[0][lc + 7][lr] = ra1.w;
        Bs[0][lc + 0][lr] = rb0.x; Bs[0][lc + 1][lr] = rb0.y;
        Bs[0][lc + 2][lr] = rb0.z; Bs[0][lc + 3][lr] = rb0.w;
        Bs[0][lc + 4][lr] = rb1.x; Bs[0][lc + 5][lr] = rb1.y;
        Bs[0][lc + 6][lr] = rb1.z; Bs[0][lc + 7][lr] = rb1.w;
        __syncthreads();

        int buf = 0;
        #pragma unroll 1
        for (int kt = 0; kt < K_DIM; kt += BK) {
            const bool has_next = (kt + BK < K_DIM);
            if (has_next) {
                ra0 = *(const float4*)(xp + kt + BK);
                ra1 = *(const float4*)(xp + kt + BK + 4);
                rb0 = *(const float4*)(ep + kt + BK);
                rb1 = *(const float4*)(ep + kt + BK + 4);
            }
            #pragma unroll
            for (int k = 0; k < BK; k++) {
                float4 a0 = *(const float4*)&As[buf][k][ty * TM];
                float4 a1 = *(const float4*)&As[buf][k][ty * TM + 4];
                float4 b0 = *(const float4*)&Bs[buf][k][tx * TN];
                float4 b1 = *(const float4*)&Bs[buf][k][tx * TN + 4];
                float av[TM] = {a0.x, a0.y, a0.z, a0.w, a1.x, a1.y, a1.z, a1.w};
                float bv[TN] = {b0.x, b0.y, b0.z, b0.w, b1.x, b1.y, b1.z, b1.w};
                #pragma unroll
                for (int i = 0; i < TM; i++)
                    #pragma unroll
                    for (int j = 0; j < TN; j++)
                        acc[i][j] = fmaf(av[i], bv[j], acc[i][j]);
            }
            if (has_next) {
                const int nb = buf ^ 1;
                As[nb][lc + 0][lr] = ra0.x; As[nb][lc + 1][lr] = ra0.y;
                As[nb][lc + 2][lr] = ra0.z; As[nb][lc + 3][lr] = ra0.w;
                As[nb][lc + 4][lr] = ra1.x; As[nb][lc + 5][lr] = ra1.y;
                As[nb][lc + 6][lr] = ra1.z; As[nb][lc + 7][lr] = ra1.w;
                Bs[nb][lc + 0][lr] = rb0.x; Bs[nb][lc + 1][lr] = rb0.y;
                Bs[nb][lc + 2][lr] = rb0.z; Bs[nb][lc + 3][lr] = rb0.w;
                Bs[nb][lc + 4][lr] = rb1.x; Bs[nb][lc + 5][lr] = rb1.y;
                Bs[nb][lc + 6][lr] = rb1.z; Bs[nb][lc + 7][lr] = rb1.w;
                __syncthreads();
            }
            buf ^= 1;
        }

        // argmin update: dist = e_sq[n] - 2*dot (x_sq is row-constant)
        #pragma unroll
        for (int j = 0; j < TN; j++) {
            const int n = nbase + tx * TN + j;
            const float es = __ldg(&g_esq[n]);
            #pragma unroll
            for (int i = 0; i < TM; i++) {
                float d = fmaf(-2.f, acc[i][j], es);
                if (d < bestv[i]) { bestv[i] = d; besti[i] = (unsigned)n; }
            }
        }
        __syncthreads();   // all threads done with both smem buffers before next tile's stores
    }

    // cross-thread (16 col-groups) reduction per row, then one atomicMin per row
    #pragma unroll
    for (int i = 0; i < TM; i++)
        red[tx][ty * TM + i] = pack_key(bestv[i], besti[i]);
    __syncthreads();
    if (tid < BM) {
        unsigned long long b = red[0][tid];
        #pragma unroll
        for (int j = 1; j < 16; j++) {
            unsigned long long c = red[j][tid];
            if (c < b) b = c;
        }
        atomicMin(&g_best[m0 + tid], b);
    }
}

// Epilogue: gather codebook rows; optionally append indices (cast to float).
__global__ void vq_gather_kernel(const float* __restrict__ embed, float* __restrict__ out,
                                 int write_idx) {
    const int r = blockIdx.x;
    const unsigned int idx = (unsigned int)(g_best[r] & 0xFFFFFFFFull);
    out[(size_t)r * K_DIM + threadIdx.x] = embed[(size_t)idx * K_DIM + threadIdx.x];
    if (write_idx && threadIdx.x == 0)
        out[(size_t)M_ROWS * K_DIM + r] = (float)idx;
}

extern "C" void kernel_launch(void* const* d_in, const int* in_sizes, int n_in,
                              void* d_out, int out_size) {
    const float* x = (const float*)d_in[0];      // [8,1024,256] f32
    const float* embed = (const float*)d_in[1];  // [8192,256] f32
    float* out = (float*)d_out;

    vq_init_kernel<<<1024, 256>>>(embed);

    dim3 grid(M_ROWS / BM, NSPLIT);
    vq_argmin_kernel<<<grid, 256>>>(x, embed);

    const int write_idx = (out_size >= M_ROWS * K_DIM + M_ROWS) ? 1 : 0;
    vq_gather_kernel<<<M_ROWS, K_DIM>>>(embed, out, write_idx);
}

// round 5
// speedup vs baseline: 1.0136x; 1.0136x over previous
#include <cuda_runtime.h>

#define M_ROWS 8192
#define N_CODES 8192
#define K_DIM 256

#define BM 128
#define BN 128
#define BK 16
#define TM 8
#define TN 8
#define NSPLIT 4
#define NT_PER (N_CODES / NSPLIT)

typedef unsigned long long u64;

__device__ float g_esq[N_CODES];
__device__ unsigned long long g_best[M_ROWS];

__device__ __forceinline__ u64 ffma2(u64 a, u64 b, u64 c) {
    u64 d;
    asm("fma.rn.f32x2 %0, %1, %2, %3;" : "=l"(d) : "l"(a), "l"(b), "l"(c));
    return d;
}

__device__ __forceinline__ u64 dup2(float v) {
    u64 d;
    asm("mov.b64 %0, {%1, %1};" : "=l"(d) : "f"(v));
    return d;
}

__device__ __forceinline__ unsigned long long pack_key(float v, unsigned int idx) {
    unsigned int u = __float_as_uint(v);
    u = (u & 0x80000000u) ? ~u : (u | 0x80000000u);   // order-preserving float->uint
    return ((unsigned long long)u << 32) | (unsigned long long)idx;
}

// Prologue: e_sq per code (one warp per code) + reset g_best.
__global__ void vq_init_kernel(const float* __restrict__ embed) {
    int gtid = blockIdx.x * blockDim.x + threadIdx.x;
    int warp = gtid >> 5;
    int lane = gtid & 31;
    if (warp < N_CODES) {
        const float* e = embed + (size_t)warp * K_DIM;
        float s = 0.f;
        #pragma unroll
        for (int k = lane * 4; k < K_DIM; k += 128) {
            float4 v = *(const float4*)(e + k);
            s += v.x * v.x + v.y * v.y + v.z * v.z + v.w * v.w;
        }
        #pragma unroll
        for (int o = 16; o > 0; o >>= 1) s += __shfl_xor_sync(0xffffffffu, s, o);
        if (lane == 0) g_esq[warp] = s;
    }
    if (gtid < M_ROWS) g_best[gtid] = 0xFFFFFFFFFFFFFFFFull;
}

// Fused GEMM + argmin, FFMA2 (packed f32x2) mainloop.
// Accumulators packed along M: acc2[i2][j] = (dot[2*i2][j], dot[2*i2+1][j]).
__global__ __launch_bounds__(256, 2)
void vq_argmin_kernel(const float* __restrict__ x, const float* __restrict__ embed) {
    __shared__ float As[2][BK][BM];
    __shared__ float Bs[2][BK][BN];
    __shared__ unsigned long long red[16][BM];

    const int m0 = blockIdx.x * BM;
    const int n_begin = blockIdx.y * NT_PER;

    const int tid = threadIdx.x;
    const int tx = tid & 15;
    const int ty = tid >> 4;

    const int lr = tid >> 1;          // load row 0..127
    const int lc = (tid & 1) * 8;     // k offset 0 or 8

    const float* xp = x + (size_t)(m0 + lr) * K_DIM + lc;

    float bestv[TM];
    unsigned int besti[TM];
    #pragma unroll
    for (int i = 0; i < TM; i++) { bestv[i] = 3.4e38f; besti[i] = 0u; }

    for (int nt0 = 0; nt0 < NT_PER; nt0 += BN) {
        const int nbase = n_begin + nt0;
        const float* ep = embed + (size_t)(nbase + lr) * K_DIM + lc;

        u64 acc2[TM / 2][TN];
        #pragma unroll
        for (int i = 0; i < TM / 2; i++)
            #pragma unroll
            for (int j = 0; j < TN; j++) acc2[i][j] = 0ull;   // (0.f, 0.f)

        // prefetch k-tile 0 into registers, store to buffer 0
        float4 ra0 = *(const float4*)(xp + 0);
        float4 ra1 = *(const float4*)(xp + 4);
        float4 rb0 = *(const float4*)(ep + 0);
        float4 rb1 = *(const float4*)(ep + 4);

        As[0][lc + 0][lr] = ra0.x; As[0][lc + 1][lr] = ra0.y;
        As[0][lc + 2][lr] = ra0.z; As[0][lc + 3][lr] = ra0.w;
        As[0][lc + 4][lr] = ra1.x; As[0][lc + 5][lr] = ra1.y;
        As[0][lc + 6][lr] = ra1.z; As[0][lc + 7][lr] = ra1.w;
        Bs[0][lc + 0][lr] = rb0.x; Bs[0][lc + 1][lr] = rb0.y;
        Bs[0][lc + 2][lr] = rb0.z; Bs[0][lc + 3][lr] = rb0.w;
        Bs[0][lc + 4][lr] = rb1.x; Bs[0][lc + 5][lr] = rb1.y;
        Bs[0][lc + 6][lr] = rb1.z; Bs[0][lc + 7][lr] = rb1.w;
        __syncthreads();

        int buf = 0;
        #pragma unroll 1
        for (int kt = 0; kt < K_DIM; kt += BK) {
            const bool has_next = (kt + BK < K_DIM);
            if (has_next) {
                ra0 = *(const float4*)(xp + kt + BK);
                ra1 = *(const float4*)(xp + kt + BK + 4);
                rb0 = *(const float4*)(ep + kt + BK);
                rb1 = *(const float4*)(ep + kt + BK + 4);
            }
            #pragma unroll
            for (int k = 0; k < BK; k++) {
                // A row pairs: 8 consecutive rows -> 4 packed f32x2 (2x LDS.128)
                ulonglong2 a01 = *(const ulonglong2*)&As[buf][k][ty * TM];
                ulonglong2 a23 = *(const ulonglong2*)&As[buf][k][ty * TM + 4];
                u64 ap[TM / 2] = {a01.x, a01.y, a23.x, a23.y};
                // B values: 8 floats (2x LDS.128), each duplicated into both lanes
                float4 b0 = *(const float4*)&Bs[buf][k][tx * TN];
                float4 b1 = *(const float4*)&Bs[buf][k][tx * TN + 4];
                u64 bd[TN] = {dup2(b0.x), dup2(b0.y), dup2(b0.z), dup2(b0.w),
                              dup2(b1.x), dup2(b1.y), dup2(b1.z), dup2(b1.w)};
                #pragma unroll
                for (int i = 0; i < TM / 2; i++)
                    #pragma unroll
                    for (int j = 0; j < TN; j++)
                        acc2[i][j] = ffma2(ap[i], bd[j], acc2[i][j]);
            }
            if (has_next) {
                const int nb = buf ^ 1;
                As[nb][lc + 0][lr] = ra0.x; As[nb][lc + 1][lr] = ra0.y;
                As[nb][lc + 2][lr] = ra0.z; As[nb][lc + 3][lr] = ra0.w;
                As[nb][lc + 4][lr] = ra1.x; As[nb][lc + 5][lr] = ra1.y;
                As[nb][lc + 6][lr] = ra1.z; As[nb][lc + 7][lr] = ra1.w;
                Bs[nb][lc + 0][lr] = rb0.x; Bs[nb][lc + 1][lr] = rb0.y;
                Bs[nb][lc + 2][lr] = rb0.z; Bs[nb][lc + 3][lr] = rb0.w;
                Bs[nb][lc + 4][lr] = rb1.x; Bs[nb][lc + 5][lr] = rb1.y;
                Bs[nb][lc + 6][lr] = rb1.z; Bs[nb][lc + 7][lr] = rb1.w;
                __syncthreads();
            }
            buf ^= 1;
        }

        // argmin update: dist = e_sq[n] - 2*dot (x_sq is row-constant)
        #pragma unroll
        for (int j = 0; j < TN; j++) {
            const int n = nbase + tx * TN + j;
            const float es = __ldg(&g_esq[n]);
            #pragma unroll
            for (int i2 = 0; i2 < TM / 2; i2++) {
                const float dlo = __uint_as_float((unsigned)(acc2[i2][j] & 0xFFFFFFFFull));
                const float dhi = __uint_as_float((unsigned)(acc2[i2][j] >> 32));
                float d0 = fmaf(-2.f, dlo, es);
                float d1 = fmaf(-2.f, dhi, es);
                if (d0 < bestv[2 * i2 + 0]) { bestv[2 * i2 + 0] = d0; besti[2 * i2 + 0] = (unsigned)n; }
                if (d1 < bestv[2 * i2 + 1]) { bestv[2 * i2 + 1] = d1; besti[2 * i2 + 1] = (unsigned)n; }
            }
        }
        __syncthreads();   // all threads done with both smem buffers before next tile's stores
    }

    // cross-thread (16 col-groups) reduction per row, then one atomicMin per row
    #pragma unroll
    for (int i = 0; i < TM; i++)
        red[tx][ty * TM + i] = pack_key(bestv[i], besti[i]);
    __syncthreads();
    if (tid < BM) {
        unsigned long long b = red[0][tid];
        #pragma unroll
        for (int j = 1; j < 16; j++) {
            unsigned long long c = red[j][tid];
            if (c < b) b = c;
        }
        atomicMin(&g_best[m0 + tid], b);
    }
}

// Epilogue: gather codebook rows; optionally append indices (cast to float).
__global__ void vq_gather_kernel(const float* __restrict__ embed, float* __restrict__ out,
                                 int write_idx) {
    const int r = blockIdx.x;
    const unsigned int idx = (unsigned int)(g_best[r] & 0xFFFFFFFFull);
    out[(size_t)r * K_DIM + threadIdx.x] = embed[(size_t)idx * K_DIM + threadIdx.x];
    if (write_idx && threadIdx.x == 0)
        out[(size_t)M_ROWS * K_DIM + r] = (float)idx;
}

extern "C" void kernel_launch(void* const* d_in, const int* in_sizes, int n_in,
                              void* d_out, int out_size) {
    const float* x = (const float*)d_in[0];      // [8,1024,256] f32
    const float* embed = (const float*)d_in[1];  // [8192,256] f32
    float* out = (float*)d_out;

    vq_init_kernel<<<1024, 256>>>(embed);

    dim3 grid(M_ROWS / BM, NSPLIT);
    vq_argmin_kernel<<<grid, 256>>>(x, embed);

    const int write_idx = (out_size >= M_ROWS * K_DIM + M_ROWS) ? 1 : 0;
    vq_gather_kernel<<<M_ROWS, K_DIM>>>(embed, out, write_idx);
}

// round 7
// speedup vs baseline: 1.2870x; 1.2697x over previous
#include <cuda_runtime.h>
#include <cuda_bf16.h>
#include <stdint.h>

#define M_ROWS 8192
#define N_CODES 8192
#define K_DIM 256

#define BM 128
#define BN 128
#define KC 64                        // bf16 K elems per chunk (128 B rows)
#define NCHUNK (K_DIM / KC)          // 4
#define NPAIRS 6
#define TILE_BYTES (128 * 128)       // 128 rows x 128 bytes
#define SMEM_DYN (12 * TILE_BYTES)   // 2 buffers x (3 A + 3 B) tiles = 192 KB

typedef unsigned long long u64;

__device__ float g_esq[N_CODES];
__device__ unsigned long long g_best[M_ROWS];
__device__ __nv_bfloat16 g_xs[3][M_ROWS * K_DIM];
__device__ __nv_bfloat16 g_es[3][N_CODES * K_DIM];

// ---------------- baseline-PTX helpers (valid on plain sm_103 target) ----------------

__device__ __forceinline__ uint32_t smem_u32(const void* p) {
    uint32_t a;
    asm("{ .reg .u64 t; cvta.to.shared.u64 t, %1; cvt.u32.u64 %0, t; }" : "=r"(a) : "l"(p));
    return a;
}

__device__ __forceinline__ void cp16(uint32_t dst, const void* src) {
    asm volatile("cp.async.cg.shared.global [%0], [%1], 16;" :: "r"(dst), "l"(src));
}
__device__ __forceinline__ void cp_commit() { asm volatile("cp.async.commit_group;" ::: "memory"); }
template <int N> __device__ __forceinline__ void cp_wait() {
    asm volatile("cp.async.wait_group %0;" :: "n"(N) : "memory");
}

__device__ __forceinline__ void ldsm4(uint32_t& r0, uint32_t& r1, uint32_t& r2, uint32_t& r3,
                                      uint32_t addr) {
    asm volatile("ldmatrix.sync.aligned.m8n8.x4.shared.b16 {%0,%1,%2,%3}, [%4];"
                 : "=r"(r0), "=r"(r1), "=r"(r2), "=r"(r3) : "r"(addr));
}

__device__ __forceinline__ void mma16816(float* d, const uint32_t* a, uint32_t b0, uint32_t b1) {
    asm volatile(
        "mma.sync.aligned.m16n8k16.row.col.f32.bf16.bf16.f32 "
        "{%0,%1,%2,%3}, {%4,%5,%6,%7}, {%8,%9}, {%0,%1,%2,%3};"
        : "+f"(d[0]), "+f"(d[1]), "+f"(d[2]), "+f"(d[3])
        : "r"(a[0]), "r"(a[1]), "r"(a[2]), "r"(a[3]), "r"(b0), "r"(b1));
}

__device__ __forceinline__ u64 pack_key(float v, unsigned int idx) {
    unsigned int u = __float_as_uint(v);
    u = (u & 0x80000000u) ? ~u : (u | 0x80000000u);
    return ((u64)u << 32) | (u64)idx;
}

__device__ __forceinline__ u64 u64min(u64 a, u64 b) { return a < b ? a : b; }

// ---------------- Prologue: e_sq + g_best init ----------------

__global__ void vq_init_kernel(const float* __restrict__ embed) {
    int gtid = blockIdx.x * blockDim.x + threadIdx.x;
    int warp = gtid >> 5;
    int lane = gtid & 31;
    if (warp < N_CODES) {
        const float* e = embed + (size_t)warp * K_DIM;
        float s = 0.f;
        #pragma unroll
        for (int k = lane * 4; k < K_DIM; k += 128) {
            float4 v = *(const float4*)(e + k);
            s += v.x * v.x + v.y * v.y + v.z * v.z + v.w * v.w;
        }
        #pragma unroll
        for (int o = 16; o > 0; o >>= 1) s += __shfl_xor_sync(0xffffffffu, s, o);
        if (lane == 0) g_esq[warp] = s;
    }
    if (gtid < M_ROWS) g_best[gtid] = 0xFFFFFFFFFFFFFFFFull;
}

// ---------------- Prologue: 3-way bf16 split of x and embed ----------------

__global__ void vq_split_kernel(const float* __restrict__ x, const float* __restrict__ embed) {
    const int gtid = blockIdx.x * blockDim.x + threadIdx.x;
    const int M4 = M_ROWS * K_DIM / 4;
    const int T4 = (M_ROWS + N_CODES) * K_DIM / 4;
    if (gtid >= T4) return;
    const float4* src;
    __nv_bfloat16 *d0, *d1, *d2;
    int q;
    if (gtid < M4) {
        q = gtid; src = (const float4*)x;
        d0 = g_xs[0]; d1 = g_xs[1]; d2 = g_xs[2];
    } else {
        q = gtid - M4; src = (const float4*)embed;
        d0 = g_es[0]; d1 = g_es[1]; d2 = g_es[2];
    }
    float4 v = __ldg(&src[q]);
    float f[4] = {v.x, v.y, v.z, v.w};
    ushort4 ua, ub, uc;
    unsigned short* pa = (unsigned short*)&ua;
    unsigned short* pb = (unsigned short*)&ub;
    unsigned short* pc = (unsigned short*)&uc;
    #pragma unroll
    for (int i = 0; i < 4; i++) {
        __nv_bfloat16 a = __float2bfloat16(f[i]);
        float r = f[i] - __bfloat162float(a);        // exact
        __nv_bfloat16 b = __float2bfloat16(r);
        float r2 = r - __bfloat162float(b);          // exact
        __nv_bfloat16 c = __float2bfloat16(r2);
        pa[i] = __bfloat16_as_ushort(a);
        pb[i] = __bfloat16_as_ushort(b);
        pc[i] = __bfloat16_as_ushort(c);
    }
    *(ushort4*)(&d0[(size_t)q * 4]) = ua;
    *(ushort4*)(&d1[(size_t)q * 4]) = ub;
    *(ushort4*)(&d2[(size_t)q * 4]) = uc;
}

// ---------------- Main: mma.sync 6-pass split GEMM + fused argmin ----------------

__global__ __launch_bounds__(256) void vq_mma_kernel() {
    extern __shared__ char tiles[];
    __shared__ float esq_s[BN];
    __shared__ u64 red[2][BM];

    const int tid = threadIdx.x;
    const int wid = tid >> 5;
    const int lane = tid & 31;
    const int m0 = blockIdx.x * BM;
    const int n0 = blockIdx.y * BN;
    const int wm0 = (wid & 3) * 32;        // warp M origin (4 warps in M)
    const int wn0 = (wid >> 2) * 64;       // warp N origin (2 warps in N)

    if (tid < BN) esq_s[tid] = g_esq[n0 + tid];

    const uint32_t tiles_base = smem_u32(tiles);

    // tile fill mapping: row = tid>>1 (0..127), 64-byte half = tid&1, SW128 swizzle
    const int lrow = tid >> 1;
    const int lhalf = tid & 1;
    uint32_t st_off[4];
    {
        const uint32_t off0 = (uint32_t)lrow * 128u + (uint32_t)lhalf * 64u;
        #pragma unroll
        for (int i = 0; i < 4; i++) {
            uint32_t o = off0 + i * 16u;
            st_off[i] = o ^ ((o >> 3) & 0x70u);
        }
    }
    const size_t a_off = (size_t)(m0 + lrow) * K_DIM + lhalf * 32;
    const size_t b_off = (size_t)(n0 + lrow) * K_DIM + lhalf * 32;

    // ldmatrix addressing (A and B are both K-major -> identical non-trans pattern):
    // addr = tile + row*128 + ((ks*32 + (lane>>4)*16) ^ ((row&7)*16))
    const int l15 = lane & 15;
    const int hi16 = (lane >> 4) * 16;
    uint32_t arow[2], arx[2], brow[4], brx[4];
    #pragma unroll
    for (int mi = 0; mi < 2; mi++) {
        int r = wm0 + mi * 16 + l15;
        arow[mi] = (uint32_t)r * 128u;
        arx[mi] = (uint32_t)(r & 7) * 16u;
    }
    #pragma unroll
    for (int g = 0; g < 4; g++) {
        int r = wn0 + g * 16 + l15;
        brow[g] = (uint32_t)r * 128u;
        brx[g] = (uint32_t)(r & 7) * 16u;
    }

    float acc[2][8][4];
    #pragma unroll
    for (int mi = 0; mi < 2; mi++)
        #pragma unroll
        for (int nj = 0; nj < 8; nj++)
            #pragma unroll
            for (int q = 0; q < 4; q++) acc[mi][nj][q] = 0.f;

    // split product pairs: aa', ab', ba', ac', bb', ca'
    const int pa6[NPAIRS] = {0, 0, 1, 0, 1, 2};
    const int pb6[NPAIRS] = {0, 1, 0, 2, 1, 0};

    // issue chunk-0 copies
    {
        #pragma unroll
        for (int s = 0; s < 3; s++) {
            const __nv_bfloat16* ga = &g_xs[s][a_off];
            const __nv_bfloat16* gb = &g_es[s][b_off];
            uint32_t ta = tiles_base + (s)*TILE_BYTES;
            uint32_t tb = tiles_base + (3 + s) * TILE_BYTES;
            #pragma unroll
            for (int i = 0; i < 4; i++) {
                cp16(ta + st_off[i], ga + i * 8);
                cp16(tb + st_off[i], gb + i * 8);
            }
        }
        cp_commit();
    }

    #pragma unroll 1
    for (int c = 0; c < NCHUNK; c++) {
        const int buf = c & 1;
        if (c + 1 < NCHUNK) {
            const int kofs = (c + 1) * KC;
            const int nb = buf ^ 1;
            #pragma unroll
            for (int s = 0; s < 3; s++) {
                const __nv_bfloat16* ga = &g_xs[s][a_off + kofs];
                const __nv_bfloat16* gb = &g_es[s][b_off + kofs];
                uint32_t ta = tiles_base + (nb * 6 + s) * TILE_BYTES;
                uint32_t tb = tiles_base + (nb * 6 + 3 + s) * TILE_BYTES;
                #pragma unroll
                for (int i = 0; i < 4; i++) {
                    cp16(ta + st_off[i], ga + i * 8);
                    cp16(tb + st_off[i], gb + i * 8);
                }
            }
            cp_commit();
            cp_wait<1>();     // chunk c resident, chunk c+1 in flight
        } else {
            cp_wait<0>();
        }
        __syncthreads();

        #pragma unroll
        for (int p = 0; p < NPAIRS; p++) {
            const uint32_t ta = tiles_base + (buf * 6 + pa6[p]) * TILE_BYTES;
            const uint32_t tb = tiles_base + (buf * 6 + 3 + pb6[p]) * TILE_BYTES;
            #pragma unroll
            for (int ks = 0; ks < 4; ks++) {
                const uint32_t kc = (uint32_t)(ks * 32 + hi16);
                uint32_t a[2][4], b[4][4];
                #pragma unroll
                for (int mi = 0; mi < 2; mi++)
                    ldsm4(a[mi][0], a[mi][1], a[mi][2], a[mi][3],
                          ta + arow[mi] + (kc ^ arx[mi]));
                #pragma unroll
                for (int g = 0; g < 4; g++)
                    ldsm4(b[g][0], b[g][1], b[g][2], b[g][3],
                          tb + brow[g] + (kc ^ brx[g]));
                #pragma unroll
                for (int mi = 0; mi < 2; mi++)
                    #pragma unroll
                    for (int g = 0; g < 4; g++) {
                        mma16816(acc[mi][g * 2 + 0], a[mi], b[g][0], b[g][2]);
                        mma16816(acc[mi][g * 2 + 1], a[mi], b[g][1], b[g][3]);
                    }
            }
        }
        __syncthreads();   // all warps done reading buf before it is overwritten
    }

    // ---- fused argmin epilogue: dist = e_sq[n] - 2*dot ----
    float bestv[4];
    unsigned besti[4];
    #pragma unroll
    for (int q = 0; q < 4; q++) { bestv[q] = 3.4e38f; besti[q] = 0u; }

    const int cbase = wn0 + (lane & 3) * 2;
    #pragma unroll
    for (int mi = 0; mi < 2; mi++) {
        #pragma unroll
        for (int nj = 0; nj < 8; nj++) {
            const int nc = cbase + nj * 8;
            const float e0 = esq_s[nc], e1 = esq_s[nc + 1];
            const float d00 = fmaf(-2.f, acc[mi][nj][0], e0);
            const float d01 = fmaf(-2.f, acc[mi][nj][1], e1);
            const float d10 = fmaf(-2.f, acc[mi][nj][2], e0);
            const float d11 = fmaf(-2.f, acc[mi][nj][3], e1);
            const unsigned gn0 = (unsigned)(n0 + nc);
            if (d00 < bestv[mi * 2 + 0]) { bestv[mi * 2 + 0] = d00; besti[mi * 2 + 0] = gn0; }
            if (d01 < bestv[mi * 2 + 0]) { bestv[mi * 2 + 0] = d01; besti[mi * 2 + 0] = gn0 + 1; }
            if (d10 < bestv[mi * 2 + 1]) { bestv[mi * 2 + 1] = d10; besti[mi * 2 + 1] = gn0; }
            if (d11 < bestv[mi * 2 + 1]) { bestv[mi * 2 + 1] = d11; besti[mi * 2 + 1] = gn0 + 1; }
        }
    }

    u64 key[4];
    #pragma unroll
    for (int q = 0; q < 4; q++) key[q] = pack_key(bestv[q], besti[q]);
    #pragma unroll
    for (int o = 1; o <= 2; o <<= 1)
        #pragma unroll
        for (int q = 0; q < 4; q++)
            key[q] = u64min(key[q], __shfl_xor_sync(0xffffffffu, key[q], o));

    if ((lane & 3) == 0) {
        const int rbase = wm0 + (lane >> 2);
        #pragma unroll
        for (int mi = 0; mi < 2; mi++)
            #pragma unroll
            for (int rh = 0; rh < 2; rh++)
                red[wid >> 2][rbase + mi * 16 + rh * 8] = key[mi * 2 + rh];
    }
    __syncthreads();
    if (tid < BM)
        atomicMin(&g_best[m0 + tid], u64min(red[0][tid], red[1][tid]));
}

// ---------------- Epilogue: gather ----------------

__global__ void vq_gather_kernel(const float* __restrict__ embed, float* __restrict__ out,
                                 int write_idx) {
    const int r = blockIdx.x;
    const unsigned int idx = (unsigned int)(g_best[r] & 0xFFFFFFFFull);
    out[(size_t)r * K_DIM + threadIdx.x] = embed[(size_t)idx * K_DIM + threadIdx.x];
    if (write_idx && threadIdx.x == 0)
        out[(size_t)M_ROWS * K_DIM + r] = (float)idx;
}

extern "C" void kernel_launch(void* const* d_in, const int* in_sizes, int n_in,
                              void* d_out, int out_size) {
    const float* x = (const float*)d_in[0];      // [8,1024,256] f32
    const float* embed = (const float*)d_in[1];  // [8192,256] f32
    float* out = (float*)d_out;

    cudaFuncSetAttribute(vq_mma_kernel, cudaFuncAttributeMaxDynamicSharedMemorySize, SMEM_DYN);

    vq_init_kernel<<<1024, 256>>>(embed);

    const int T4 = (M_ROWS + N_CODES) * K_DIM / 4;
    vq_split_kernel<<<(T4 + 255) / 256, 256>>>(x, embed);

    dim3 grid(M_ROWS / BM, N_CODES / BN);
    vq_mma_kernel<<<grid, 256, SMEM_DYN>>>();

    const int write_idx = (out_size >= M_ROWS * K_DIM + M_ROWS) ? 1 : 0;
    vq_gather_kernel<<<M_ROWS, K_DIM>>>(embed, out, write_idx);
}

// round 8
// speedup vs baseline: 2.3440x; 1.8213x over previous
#include <cuda_runtime.h>
#include <cuda_fp16.h>
#include <stdint.h>

#define M_ROWS 8192
#define N_CODES 8192
#define K_DIM 256

#define BM 128
#define BN 128
#define KC 64                        // fp16 K elems per chunk (128 B rows)
#define NCHUNK (K_DIM / KC)          // 4
#define NPAIRS 3
#define TILE_BYTES (128 * 128)       // 128 rows x 128 bytes
#define SMEM_DYN (8 * TILE_BYTES)    // 2 buffers x (2 A + 2 B) tiles = 128 KB

typedef unsigned long long u64;

__device__ float g_esq[N_CODES];
__device__ unsigned long long g_best[M_ROWS];
__device__ __half g_xs[2][M_ROWS * K_DIM];
__device__ __half g_es[2][N_CODES * K_DIM];

// ---------------- baseline-PTX helpers (valid on plain sm_103 target) ----------------

__device__ __forceinline__ uint32_t smem_u32(const void* p) {
    uint32_t a;
    asm("{ .reg .u64 t; cvta.to.shared.u64 t, %1; cvt.u32.u64 %0, t; }" : "=r"(a) : "l"(p));
    return a;
}

__device__ __forceinline__ void cp16(uint32_t dst, const void* src) {
    asm volatile("cp.async.cg.shared.global [%0], [%1], 16;" :: "r"(dst), "l"(src));
}
__device__ __forceinline__ void cp_commit() { asm volatile("cp.async.commit_group;" ::: "memory"); }
template <int N> __device__ __forceinline__ void cp_wait() {
    asm volatile("cp.async.wait_group %0;" :: "n"(N) : "memory");
}

__device__ __forceinline__ void ldsm4(uint32_t& r0, uint32_t& r1, uint32_t& r2, uint32_t& r3,
                                      uint32_t addr) {
    asm volatile("ldmatrix.sync.aligned.m8n8.x4.shared.b16 {%0,%1,%2,%3}, [%4];"
                 : "=r"(r0), "=r"(r1), "=r"(r2), "=r"(r3) : "r"(addr));
}

__device__ __forceinline__ void mma16816(float* d, const uint32_t* a, uint32_t b0, uint32_t b1) {
    asm volatile(
        "mma.sync.aligned.m16n8k16.row.col.f32.f16.f16.f32 "
        "{%0,%1,%2,%3}, {%4,%5,%6,%7}, {%8,%9}, {%0,%1,%2,%3};"
        : "+f"(d[0]), "+f"(d[1]), "+f"(d[2]), "+f"(d[3])
        : "r"(a[0]), "r"(a[1]), "r"(a[2]), "r"(a[3]), "r"(b0), "r"(b1));
}

__device__ __forceinline__ u64 pack_key(float v, unsigned int idx) {
    unsigned int u = __float_as_uint(v);
    u = (u & 0x80000000u) ? ~u : (u | 0x80000000u);
    return ((u64)u << 32) | (u64)idx;
}

__device__ __forceinline__ u64 u64min(u64 a, u64 b) { return a < b ? a : b; }

// ---------------- Prologue: e_sq + g_best init ----------------

__global__ void vq_init_kernel(const float* __restrict__ embed) {
    int gtid = blockIdx.x * blockDim.x + threadIdx.x;
    int warp = gtid >> 5;
    int lane = gtid & 31;
    if (warp < N_CODES) {
        const float* e = embed + (size_t)warp * K_DIM;
        float s = 0.f;
        #pragma unroll
        for (int k = lane * 4; k < K_DIM; k += 128) {
            float4 v = *(const float4*)(e + k);
            s += v.x * v.x + v.y * v.y + v.z * v.z + v.w * v.w;
        }
        #pragma unroll
        for (int o = 16; o > 0; o >>= 1) s += __shfl_xor_sync(0xffffffffu, s, o);
        if (lane == 0) g_esq[warp] = s;
    }
    if (gtid < M_ROWS) g_best[gtid] = 0xFFFFFFFFFFFFFFFFull;
}

// ---------------- Prologue: 2-way fp16 split of x and embed ----------------
// x = a + b + c, a = fp16(x), b = fp16(x - a) [x-a exact in fp32], |c| <= 2^-22 |x|.

__global__ void vq_split_kernel(const float* __restrict__ x, const float* __restrict__ embed) {
    const int gtid = blockIdx.x * blockDim.x + threadIdx.x;
    const int M4 = M_ROWS * K_DIM / 4;
    const int T4 = (M_ROWS + N_CODES) * K_DIM / 4;
    if (gtid >= T4) return;
    const float4* src;
    __half *d0, *d1;
    int q;
    if (gtid < M4) {
        q = gtid; src = (const float4*)x;
        d0 = g_xs[0]; d1 = g_xs[1];
    } else {
        q = gtid - M4; src = (const float4*)embed;
        d0 = g_es[0]; d1 = g_es[1];
    }
    float4 v = __ldg(&src[q]);
    float f[4] = {v.x, v.y, v.z, v.w};
    ushort4 ua, ub;
    unsigned short* pa = (unsigned short*)&ua;
    unsigned short* pb = (unsigned short*)&ub;
    #pragma unroll
    for (int i = 0; i < 4; i++) {
        __half a = __float2half_rn(f[i]);
        float r = f[i] - __half2float(a);        // exact
        __half b = __float2half_rn(r);
        pa[i] = __half_as_ushort(a);
        pb[i] = __half_as_ushort(b);
    }
    *(ushort4*)(&d0[(size_t)q * 4]) = ua;
    *(ushort4*)(&d1[(size_t)q * 4]) = ub;
}

// ---------------- Main: mma.sync 3-pass fp16-split GEMM + fused argmin ----------------

__global__ __launch_bounds__(256) void vq_mma_kernel() {
    extern __shared__ char tiles[];
    __shared__ float esq_s[BN];
    __shared__ u64 red[2][BM];

    const int tid = threadIdx.x;
    const int wid = tid >> 5;
    const int lane = tid & 31;
    const int m0 = blockIdx.x * BM;
    const int n0 = blockIdx.y * BN;
    const int wm0 = (wid & 3) * 32;        // warp M origin (4 warps in M)
    const int wn0 = (wid >> 2) * 64;       // warp N origin (2 warps in N)

    if (tid < BN) esq_s[tid] = g_esq[n0 + tid];

    const uint32_t tiles_base = smem_u32(tiles);

    // tile fill mapping: row = tid>>1 (0..127), 64-byte half = tid&1, SW128 swizzle
    const int lrow = tid >> 1;
    const int lhalf = tid & 1;
    uint32_t st_off[4];
    {
        const uint32_t off0 = (uint32_t)lrow * 128u + (uint32_t)lhalf * 64u;
        #pragma unroll
        for (int i = 0; i < 4; i++) {
            uint32_t o = off0 + i * 16u;
            st_off[i] = o ^ ((o >> 3) & 0x70u);
        }
    }
    const size_t a_off = (size_t)(m0 + lrow) * K_DIM + lhalf * 32;
    const size_t b_off = (size_t)(n0 + lrow) * K_DIM + lhalf * 32;

    // ldmatrix addressing (A and B both K-major -> identical non-trans pattern)
    const int l15 = lane & 15;
    const int hi16 = (lane >> 4) * 16;
    uint32_t arow[2], arx[2], brow[4], brx[4];
    #pragma unroll
    for (int mi = 0; mi < 2; mi++) {
        int r = wm0 + mi * 16 + l15;
        arow[mi] = (uint32_t)r * 128u;
        arx[mi] = (uint32_t)(r & 7) * 16u;
    }
    #pragma unroll
    for (int g = 0; g < 4; g++) {
        int r = wn0 + g * 16 + l15;
        brow[g] = (uint32_t)r * 128u;
        brx[g] = (uint32_t)(r & 7) * 16u;
    }

    float acc[2][8][4];
    #pragma unroll
    for (int mi = 0; mi < 2; mi++)
        #pragma unroll
        for (int nj = 0; nj < 8; nj++)
            #pragma unroll
            for (int q = 0; q < 4; q++) acc[mi][nj][q] = 0.f;

    // split product pairs: aa', ab', ba'   (dropped bb' + c-terms ~ 2^-22)
    const int pa3[NPAIRS] = {0, 0, 1};
    const int pb3[NPAIRS] = {0, 1, 0};

    // issue chunk-0 copies
    {
        #pragma unroll
        for (int s = 0; s < 2; s++) {
            const __half* ga = &g_xs[s][a_off];
            const __half* gb = &g_es[s][b_off];
            uint32_t ta = tiles_base + (s)*TILE_BYTES;
            uint32_t tb = tiles_base + (2 + s) * TILE_BYTES;
            #pragma unroll
            for (int i = 0; i < 4; i++) {
                cp16(ta + st_off[i], ga + i * 8);
                cp16(tb + st_off[i], gb + i * 8);
            }
        }
        cp_commit();
    }

    #pragma unroll 1
    for (int c = 0; c < NCHUNK; c++) {
        const int buf = c & 1;
        if (c + 1 < NCHUNK) {
            const int kofs = (c + 1) * KC;
            const int nb = buf ^ 1;
            #pragma unroll
            for (int s = 0; s < 2; s++) {
                const __half* ga = &g_xs[s][a_off + kofs];
                const __half* gb = &g_es[s][b_off + kofs];
                uint32_t ta = tiles_base + (nb * 4 + s) * TILE_BYTES;
                uint32_t tb = tiles_base + (nb * 4 + 2 + s) * TILE_BYTES;
                #pragma unroll
                for (int i = 0; i < 4; i++) {
                    cp16(ta + st_off[i], ga + i * 8);
                    cp16(tb + st_off[i], gb + i * 8);
                }
            }
            cp_commit();
            cp_wait<1>();     // chunk c resident, chunk c+1 in flight
        } else {
            cp_wait<0>();
        }
        __syncthreads();

        #pragma unroll
        for (int p = 0; p < NPAIRS; p++) {
            const uint32_t ta = tiles_base + (buf * 4 + pa3[p]) * TILE_BYTES;
            const uint32_t tb = tiles_base + (buf * 4 + 2 + pb3[p]) * TILE_BYTES;
            #pragma unroll
            for (int ks = 0; ks < 4; ks++) {
                const uint32_t kc = (uint32_t)(ks * 32 + hi16);
                uint32_t a[2][4], b[4][4];
                #pragma unroll
                for (int mi = 0; mi < 2; mi++)
                    ldsm4(a[mi][0], a[mi][1], a[mi][2], a[mi][3],
                          ta + arow[mi] + (kc ^ arx[mi]));
                #pragma unroll
                for (int g = 0; g < 4; g++)
                    ldsm4(b[g][0], b[g][1], b[g][2], b[g][3],
                          tb + brow[g] + (kc ^ brx[g]));
                #pragma unroll
                for (int mi = 0; mi < 2; mi++)
                    #pragma unroll
                    for (int g = 0; g < 4; g++) {
                        mma16816(acc[mi][g * 2 + 0], a[mi], b[g][0], b[g][2]);
                        mma16816(acc[mi][g * 2 + 1], a[mi], b[g][1], b[g][3]);
                    }
            }
        }
        __syncthreads();   // all warps done reading buf before it is overwritten
    }

    // ---- fused argmin epilogue: dist = e_sq[n] - 2*dot ----
    float bestv[4];
    unsigned besti[4];
    #pragma unroll
    for (int q = 0; q < 4; q++) { bestv[q] = 3.4e38f; besti[q] = 0u; }

    const int cbase = wn0 + (lane & 3) * 2;
    #pragma unroll
    for (int mi = 0; mi < 2; mi++) {
        #pragma unroll
        for (int nj = 0; nj < 8; nj++) {
            const int nc = cbase + nj * 8;
            const float e0 = esq_s[nc], e1 = esq_s[nc + 1];
            const float d00 = fmaf(-2.f, acc[mi][nj][0], e0);
            const float d01 = fmaf(-2.f, acc[mi][nj][1], e1);
            const float d10 = fmaf(-2.f, acc[mi][nj][2], e0);
            const float d11 = fmaf(-2.f, acc[mi][nj][3], e1);
            const unsigned gn0 = (unsigned)(n0 + nc);
            if (d00 < bestv[mi * 2 + 0]) { bestv[mi * 2 + 0] = d00; besti[mi * 2 + 0] = gn0; }
            if (d01 < bestv[mi * 2 + 0]) { bestv[mi * 2 + 0] = d01; besti[mi * 2 + 0] = gn0 + 1; }
            if (d10 < bestv[mi * 2 + 1]) { bestv[mi * 2 + 1] = d10; besti[mi * 2 + 1] = gn0; }
            if (d11 < bestv[mi * 2 + 1]) { bestv[mi * 2 + 1] = d11; besti[mi * 2 + 1] = gn0 + 1; }
        }
    }

    u64 key[4];
    #pragma unroll
    for (int q = 0; q < 4; q++) key[q] = pack_key(bestv[q], besti[q]);
    #pragma unroll
    for (int o = 1; o <= 2; o <<= 1)
        #pragma unroll
        for (int q = 0; q < 4; q++)
            key[q] = u64min(key[q], __shfl_xor_sync(0xffffffffu, key[q], o));

    if ((lane & 3) == 0) {
        const int rbase = wm0 + (lane >> 2);
        #pragma unroll
        for (int mi = 0; mi < 2; mi++)
            #pragma unroll
            for (int rh = 0; rh < 2; rh++)
                red[wid >> 2][rbase + mi * 16 + rh * 8] = key[mi * 2 + rh];
    }
    __syncthreads();
    if (tid < BM)
        atomicMin(&g_best[m0 + tid], u64min(red[0][tid], red[1][tid]));
}

// ---------------- Epilogue: gather ----------------

__global__ void vq_gather_kernel(const float* __restrict__ embed, float* __restrict__ out,
                                 int write_idx) {
    const int r = blockIdx.x;
    const unsigned int idx = (unsigned int)(g_best[r] & 0xFFFFFFFFull);
    out[(size_t)r * K_DIM + threadIdx.x] = embed[(size_t)idx * K_DIM + threadIdx.x];
    if (write_idx && threadIdx.x == 0)
        out[(size_t)M_ROWS * K_DIM + r] = (float)idx;
}

extern "C" void kernel_launch(void* const* d_in, const int* in_sizes, int n_in,
                              void* d_out, int out_size) {
    const float* x = (const float*)d_in[0];      // [8,1024,256] f32
    const float* embed = (const float*)d_in[1];  // [8192,256] f32
    float* out = (float*)d_out;

    cudaFuncSetAttribute(vq_mma_kernel, cudaFuncAttributeMaxDynamicSharedMemorySize, SMEM_DYN);

    vq_init_kernel<<<1024, 256>>>(embed);

    const int T4 = (M_ROWS + N_CODES) * K_DIM / 4;
    vq_split_kernel<<<(T4 + 255) / 256, 256>>>(x, embed);

    dim3 grid(M_ROWS / BM, N_CODES / BN);
    vq_mma_kernel<<<grid, 256, SMEM_DYN>>>();

    const int write_idx = (out_size >= M_ROWS * K_DIM + M_ROWS) ? 1 : 0;
    vq_gather_kernel<<<M_ROWS, K_DIM>>>(embed, out, write_idx);
}

// round 9
// speedup vs baseline: 3.2039x; 1.3669x over previous
#include <cuda_runtime.h>
#include <cuda_fp16.h>
#include <stdint.h>

#define M_ROWS 8192
#define N_CODES 8192
#define K_DIM 256

#define BM 128
#define BN 128
#define NCTA_N (N_CODES / BN)        // 64
#define KC 64                        // fp16 K elems per chunk (128 B rows)
#define NCHUNK (K_DIM / KC)          // 4
#define TILE_BYTES (128 * 128)       // 128 rows x 128 bytes
#define SMEM_DYN (4 * TILE_BYTES)    // 2 buffers x (1 A + 1 B) tiles = 64 KB
#define MARGIN 1.0f                  // covers worst-case fp16 screen error difference

typedef unsigned long long u64;

__device__ float g_esq[N_CODES];
__device__ u64 g_best[M_ROWS];
__device__ u64 g_cand[M_ROWS][NCTA_N][2];      // top-2 approx candidates per (row, N-CTA)
__device__ __half g_xh[M_ROWS * K_DIM];
__device__ __half g_eh[N_CODES * K_DIM];

// ---------------- baseline-PTX helpers (valid on plain sm_103 target) ----------------

__device__ __forceinline__ uint32_t smem_u32(const void* p) {
    uint32_t a;
    asm("{ .reg .u64 t; cvta.to.shared.u64 t, %1; cvt.u32.u64 %0, t; }" : "=r"(a) : "l"(p));
    return a;
}

__device__ __forceinline__ void cp16(uint32_t dst, const void* src) {
    asm volatile("cp.async.cg.shared.global [%0], [%1], 16;" :: "r"(dst), "l"(src));
}
__device__ __forceinline__ void cp_commit() { asm volatile("cp.async.commit_group;" ::: "memory"); }
template <int N> __device__ __forceinline__ void cp_wait() {
    asm volatile("cp.async.wait_group %0;" :: "n"(N) : "memory");
}

__device__ __forceinline__ void ldsm4(uint32_t& r0, uint32_t& r1, uint32_t& r2, uint32_t& r3,
                                      uint32_t addr) {
    asm volatile("ldmatrix.sync.aligned.m8n8.x4.shared.b16 {%0,%1,%2,%3}, [%4];"
                 : "=r"(r0), "=r"(r1), "=r"(r2), "=r"(r3) : "r"(addr));
}

__device__ __forceinline__ void mma16816(float* d, const uint32_t* a, uint32_t b0, uint32_t b1) {
    asm volatile(
        "mma.sync.aligned.m16n8k16.row.col.f32.f16.f16.f32 "
        "{%0,%1,%2,%3}, {%4,%5,%6,%7}, {%8,%9}, {%0,%1,%2,%3};"
        : "+f"(d[0]), "+f"(d[1]), "+f"(d[2]), "+f"(d[3])
        : "r"(a[0]), "r"(a[1]), "r"(a[2]), "r"(a[3]), "r"(b0), "r"(b1));
}

__device__ __forceinline__ u64 pack_key(float v, unsigned int idx) {
    unsigned int u = __float_as_uint(v);
    u = (u & 0x80000000u) ? ~u : (u | 0x80000000u);
    return ((u64)u << 32) | (u64)idx;
}
__device__ __forceinline__ float unpack_val(u64 k) {
    unsigned int u = (unsigned int)(k >> 32);
    u = (u & 0x80000000u) ? (u & 0x7FFFFFFFu) : ~u;
    return __uint_as_float(u);
}

__device__ __forceinline__ u64 u64min(u64 a, u64 b) { return a < b ? a : b; }
__device__ __forceinline__ u64 u64max(u64 a, u64 b) { return a > b ? a : b; }

// top-2 update with one candidate
__device__ __forceinline__ void top2_push(u64& k1, u64& k2, u64 k) {
    u64 lo = u64min(k, k1);
    u64 hi = u64max(k, k1);
    k1 = lo;
    k2 = u64min(k2, hi);
}
// merge two top-2 pairs
__device__ __forceinline__ void top2_merge(u64& k1, u64& k2, u64 j1, u64 j2) {
    u64 lo = u64min(k1, j1);
    u64 hi = u64max(k1, j1);
    k1 = lo;
    k2 = u64min(u64min(k2, j2), hi);
}

// ---------------- Prologue: e_sq ----------------

__global__ void vq_init_kernel(const float* __restrict__ embed) {
    int gtid = blockIdx.x * blockDim.x + threadIdx.x;
    int warp = gtid >> 5;
    int lane = gtid & 31;
    if (warp < N_CODES) {
        const float* e = embed + (size_t)warp * K_DIM;
        float s = 0.f;
        #pragma unroll
        for (int k = lane * 4; k < K_DIM; k += 128) {
            float4 v = *(const float4*)(e + k);
            s += v.x * v.x + v.y * v.y + v.z * v.z + v.w * v.w;
        }
        #pragma unroll
        for (int o = 16; o > 0; o >>= 1) s += __shfl_xor_sync(0xffffffffu, s, o);
        if (lane == 0) g_esq[warp] = s;
    }
}

// ---------------- Prologue: fp16 convert of x and embed ----------------

__global__ void vq_convert_kernel(const float* __restrict__ x, const float* __restrict__ embed) {
    const int gtid = blockIdx.x * blockDim.x + threadIdx.x;
    const int M4 = M_ROWS * K_DIM / 4;
    const int T4 = (M_ROWS + N_CODES) * K_DIM / 4;
    if (gtid >= T4) return;
    const float4* src;
    __half* dst;
    int q;
    if (gtid < M4) { q = gtid; src = (const float4*)x; dst = g_xh; }
    else { q = gtid - M4; src = (const float4*)embed; dst = g_eh; }
    float4 v = __ldg(&src[q]);
    ushort4 ua;
    unsigned short* pa = (unsigned short*)&ua;
    pa[0] = __half_as_ushort(__float2half_rn(v.x));
    pa[1] = __half_as_ushort(__float2half_rn(v.y));
    pa[2] = __half_as_ushort(__float2half_rn(v.z));
    pa[3] = __half_as_ushort(__float2half_rn(v.w));
    *(ushort4*)(&dst[(size_t)q * 4]) = ua;
}

// ---------------- Phase 1: fp16 screening GEMM + per-CTA top-2 candidates ----------------

__global__ __launch_bounds__(256, 2) void vq_mma_kernel() {
    extern __shared__ char tiles[];
    __shared__ float esq_s[BN];
    __shared__ u64 red[2][BM][2];

    const int tid = threadIdx.x;
    const int wid = tid >> 5;
    const int lane = tid & 31;
    const int m0 = blockIdx.x * BM;
    const int n0 = blockIdx.y * BN;
    const int wm0 = (wid & 3) * 32;        // warp M origin (4 warps in M)
    const int wn0 = (wid >> 2) * 64;       // warp N origin (2 warps in N)

    if (tid < BN) esq_s[tid] = g_esq[n0 + tid];

    const uint32_t tiles_base = smem_u32(tiles);

    // tile fill mapping: row = tid>>1 (0..127), 64-byte half = tid&1, SW128 swizzle
    const int lrow = tid >> 1;
    const int lhalf = tid & 1;
    uint32_t st_off[4];
    {
        const uint32_t off0 = (uint32_t)lrow * 128u + (uint32_t)lhalf * 64u;
        #pragma unroll
        for (int i = 0; i < 4; i++) {
            uint32_t o = off0 + i * 16u;
            st_off[i] = o ^ ((o >> 3) & 0x70u);
        }
    }
    const size_t a_off = (size_t)(m0 + lrow) * K_DIM + lhalf * 32;
    const size_t b_off = (size_t)(n0 + lrow) * K_DIM + lhalf * 32;

    // ldmatrix addressing (A and B both K-major -> identical non-trans pattern)
    const int l15 = lane & 15;
    const int hi16 = (lane >> 4) * 16;
    uint32_t arow[2], arx[2], brow[4], brx[4];
    #pragma unroll
    for (int mi = 0; mi < 2; mi++) {
        int r = wm0 + mi * 16 + l15;
        arow[mi] = (uint32_t)r * 128u;
        arx[mi] = (uint32_t)(r & 7) * 16u;
    }
    #pragma unroll
    for (int g = 0; g < 4; g++) {
        int r = wn0 + g * 16 + l15;
        brow[g] = (uint32_t)r * 128u;
        brx[g] = (uint32_t)(r & 7) * 16u;
    }

    float acc[2][8][4];
    #pragma unroll
    for (int mi = 0; mi < 2; mi++)
        #pragma unroll
        for (int nj = 0; nj < 8; nj++)
            #pragma unroll
            for (int q = 0; q < 4; q++) acc[mi][nj][q] = 0.f;

    // issue chunk-0 copies
    {
        const __half* ga = &g_xh[a_off];
        const __half* gb = &g_eh[b_off];
        uint32_t ta = tiles_base;
        uint32_t tb = tiles_base + TILE_BYTES;
        #pragma unroll
        for (int i = 0; i < 4; i++) {
            cp16(ta + st_off[i], ga + i * 8);
            cp16(tb + st_off[i], gb + i * 8);
        }
        cp_commit();
    }

    #pragma unroll 1
    for (int c = 0; c < NCHUNK; c++) {
        const int buf = c & 1;
        if (c + 1 < NCHUNK) {
            const int kofs = (c + 1) * KC;
            const int nb = buf ^ 1;
            const __half* ga = &g_xh[a_off + kofs];
            const __half* gb = &g_eh[b_off + kofs];
            uint32_t ta = tiles_base + (nb * 2) * TILE_BYTES;
            uint32_t tb = tiles_base + (nb * 2 + 1) * TILE_BYTES;
            #pragma unroll
            for (int i = 0; i < 4; i++) {
                cp16(ta + st_off[i], ga + i * 8);
                cp16(tb + st_off[i], gb + i * 8);
            }
            cp_commit();
            cp_wait<1>();     // chunk c resident, chunk c+1 in flight
        } else {
            cp_wait<0>();
        }
        __syncthreads();

        const uint32_t ta = tiles_base + (buf * 2) * TILE_BYTES;
        const uint32_t tb = tiles_base + (buf * 2 + 1) * TILE_BYTES;
        #pragma unroll
        for (int ks = 0; ks < 4; ks++) {
            const uint32_t kc = (uint32_t)(ks * 32 + hi16);
            uint32_t a[2][4], b[4][4];
            #pragma unroll
            for (int mi = 0; mi < 2; mi++)
                ldsm4(a[mi][0], a[mi][1], a[mi][2], a[mi][3],
                      ta + arow[mi] + (kc ^ arx[mi]));
            #pragma unroll
            for (int g = 0; g < 4; g++)
                ldsm4(b[g][0], b[g][1], b[g][2], b[g][3],
                      tb + brow[g] + (kc ^ brx[g]));
            #pragma unroll
            for (int mi = 0; mi < 2; mi++)
                #pragma unroll
                for (int g = 0; g < 4; g++) {
                    mma16816(acc[mi][g * 2 + 0], a[mi], b[g][0], b[g][2]);
                    mma16816(acc[mi][g * 2 + 1], a[mi], b[g][1], b[g][3]);
                }
        }
        __syncthreads();   // all warps done reading buf before it is overwritten
    }

    // ---- epilogue: approx dist = e_sq[n] - 2*dot; per (row, CTA) top-2 capture ----
    const int cbase = wn0 + (lane & 3) * 2;
    #pragma unroll
    for (int mi = 0; mi < 2; mi++) {
        #pragma unroll
        for (int rh = 0; rh < 2; rh++) {
            u64 k1 = 0xFFFFFFFFFFFFFFFFull, k2 = 0xFFFFFFFFFFFFFFFFull;
            #pragma unroll
            for (int nj = 0; nj < 8; nj++) {
                const int nc = cbase + nj * 8;
                const float d0 = fmaf(-2.f, acc[mi][nj][rh * 2 + 0], esq_s[nc]);
                const float d1 = fmaf(-2.f, acc[mi][nj][rh * 2 + 1], esq_s[nc + 1]);
                top2_push(k1, k2, pack_key(d0, (unsigned)(n0 + nc)));
                top2_push(k1, k2, pack_key(d1, (unsigned)(n0 + nc + 1)));
            }
            // merge across the lane quad (lanes sharing the same row)
            #pragma unroll
            for (int o = 1; o <= 2; o <<= 1) {
                u64 j1 = __shfl_xor_sync(0xffffffffu, k1, o);
                u64 j2 = __shfl_xor_sync(0xffffffffu, k2, o);
                top2_merge(k1, k2, j1, j2);
            }
            if ((lane & 3) == 0) {
                const int row = wm0 + mi * 16 + rh * 8 + (lane >> 2);
                red[wid >> 2][row][0] = k1;
                red[wid >> 2][row][1] = k2;
            }
        }
    }
    __syncthreads();
    if (tid < BM) {
        u64 k1 = red[0][tid][0], k2 = red[0][tid][1];
        top2_merge(k1, k2, red[1][tid][0], red[1][tid][1]);
        g_cand[m0 + tid][blockIdx.y][0] = k1;
        g_cand[m0 + tid][blockIdx.y][1] = k2;
    }
}

// ---------------- Phase 2: exact fp32 rescue (one warp per row) ----------------

__global__ __launch_bounds__(256) void vq_refine_kernel(const float* __restrict__ x,
                                                        const float* __restrict__ embed) {
    const int row = blockIdx.x * 8 + (threadIdx.x >> 5);
    const int lane = threadIdx.x & 31;

    // x row into registers: 8 floats per lane
    const float4* xr = (const float4*)(x + (size_t)row * K_DIM);
    const float4 xa = __ldg(&xr[lane * 2]);
    const float4 xb = __ldg(&xr[lane * 2 + 1]);

    // load this row's 128 candidate keys (4 per lane)
    const u64* cp = &g_cand[row][0][0];
    u64 keys[4];
    #pragma unroll
    for (int i = 0; i < 4; i++) keys[i] = cp[lane + 32 * i];

    // approx min over all candidates
    u64 kmin = keys[0];
    #pragma unroll
    for (int i = 1; i < 4; i++) kmin = u64min(kmin, keys[i]);
    #pragma unroll
    for (int o = 16; o > 0; o >>= 1)
        kmin = u64min(kmin, __shfl_xor_sync(0xffffffffu, kmin, o));
    const float thresh = unpack_val(kmin) + MARGIN;

    u64 best = 0xFFFFFFFFFFFFFFFFull;
    #pragma unroll
    for (int i = 0; i < 4; i++) {
        unsigned mask = __ballot_sync(0xffffffffu, unpack_val(keys[i]) <= thresh);
        while (mask) {
            const int src = __ffs(mask) - 1;
            mask &= mask - 1;
            const unsigned idx = (unsigned)(__shfl_sync(0xffffffffu, keys[i], src) & 0xFFFFFFFFull);
            const float4* er = (const float4*)(embed + (size_t)idx * K_DIM);
            const float4 ea = __ldg(&er[lane * 2]);
            const float4 eb = __ldg(&er[lane * 2 + 1]);
            float s = xa.x * ea.x + xa.y * ea.y + xa.z * ea.z + xa.w * ea.w
                    + xb.x * eb.x + xb.y * eb.y + xb.z * eb.z + xb.w * eb.w;
            #pragma unroll
            for (int o = 16; o > 0; o >>= 1) s += __shfl_xor_sync(0xffffffffu, s, o);
            const float d = fmaf(-2.f, s, __ldg(&g_esq[idx]));
            best = u64min(best, pack_key(d, idx));
        }
    }
    if (lane == 0) g_best[row] = best;
}

// ---------------- Epilogue: gather ----------------

__global__ void vq_gather_kernel(const float* __restrict__ embed, float* __restrict__ out,
                                 int write_idx) {
    const int r = blockIdx.x;
    const unsigned int idx = (unsigned int)(g_best[r] & 0xFFFFFFFFull);
    out[(size_t)r * K_DIM + threadIdx.x] = embed[(size_t)idx * K_DIM + threadIdx.x];
    if (write_idx && threadIdx.x == 0)
        out[(size_t)M_ROWS * K_DIM + r] = (float)idx;
}

extern "C" void kernel_launch(void* const* d_in, const int* in_sizes, int n_in,
                              void* d_out, int out_size) {
    const float* x = (const float*)d_in[0];      // [8,1024,256] f32
    const float* embed = (const float*)d_in[1];  // [8192,256] f32
    float* out = (float*)d_out;

    cudaFuncSetAttribute(vq_mma_kernel, cudaFuncAttributeMaxDynamicSharedMemorySize, SMEM_DYN);

    vq_init_kernel<<<1024, 256>>>(embed);

    const int T4 = (M_ROWS + N_CODES) * K_DIM / 4;
    vq_convert_kernel<<<(T4 + 255) / 256, 256>>>(x, embed);

    dim3 grid(M_ROWS / BM, N_CODES / BN);
    vq_mma_kernel<<<grid, 256, SMEM_DYN>>>();

    vq_refine_kernel<<<M_ROWS / 8, 256>>>(x, embed);

    const int write_idx = (out_size >= M_ROWS * K_DIM + M_ROWS) ? 1 : 0;
    vq_gather_kernel<<<M_ROWS, K_DIM>>>(embed, out, write_idx);
}

// round 10
// speedup vs baseline: 4.1819x; 1.3053x over previous
#include <cuda_runtime.h>
#include <cuda_fp16.h>
#include <stdint.h>

#define M_ROWS 8192
#define N_CODES 8192
#define K_DIM 256

#define BM 128
#define BN 256
#define NCTA_N (N_CODES / BN)        // 32
#define KC 64                        // fp16 K elems per chunk (128 B rows)
#define NCHUNK (K_DIM / KC)          // 4
#define TILE_BYTES (128 * 128)       // 128 rows x 128 bytes
#define SMEM_DYN (6 * TILE_BYTES)    // 2 stages x (1 A + 2 B) tiles = 96 KB
#define MARGIN 1.0f                  // covers fp16 screen error difference

typedef unsigned long long u64;

__device__ float g_esq[N_CODES];
__device__ u64 g_cand[M_ROWS][NCTA_N][2];      // top-2 approx candidates per (row, N-CTA)
__device__ __half g_xh[M_ROWS * K_DIM];
__device__ __half g_eh[N_CODES * K_DIM];

// ---------------- baseline-PTX helpers (valid on plain sm_103 target) ----------------

__device__ __forceinline__ uint32_t smem_u32(const void* p) {
    uint32_t a;
    asm("{ .reg .u64 t; cvta.to.shared.u64 t, %1; cvt.u32.u64 %0, t; }" : "=r"(a) : "l"(p));
    return a;
}

__device__ __forceinline__ void cp16(uint32_t dst, const void* src) {
    asm volatile("cp.async.cg.shared.global [%0], [%1], 16;" :: "r"(dst), "l"(src));
}
__device__ __forceinline__ void cp_commit() { asm volatile("cp.async.commit_group;" ::: "memory"); }
template <int N> __device__ __forceinline__ void cp_wait() {
    asm volatile("cp.async.wait_group %0;" :: "n"(N) : "memory");
}

__device__ __forceinline__ void ldsm4(uint32_t& r0, uint32_t& r1, uint32_t& r2, uint32_t& r3,
                                      uint32_t addr) {
    asm volatile("ldmatrix.sync.aligned.m8n8.x4.shared.b16 {%0,%1,%2,%3}, [%4];"
                 : "=r"(r0), "=r"(r1), "=r"(r2), "=r"(r3) : "r"(addr));
}

__device__ __forceinline__ void mma16816(float* d, const uint32_t* a, uint32_t b0, uint32_t b1) {
    asm volatile(
        "mma.sync.aligned.m16n8k16.row.col.f32.f16.f16.f32 "
        "{%0,%1,%2,%3}, {%4,%5,%6,%7}, {%8,%9}, {%0,%1,%2,%3};"
        : "+f"(d[0]), "+f"(d[1]), "+f"(d[2]), "+f"(d[3])
        : "r"(a[0]), "r"(a[1]), "r"(a[2]), "r"(a[3]), "r"(b0), "r"(b1));
}

__device__ __forceinline__ u64 pack_key(float v, unsigned int idx) {
    unsigned int u = __float_as_uint(v);
    u = (u & 0x80000000u) ? ~u : (u | 0x80000000u);
    return ((u64)u << 32) | (u64)idx;
}
__device__ __forceinline__ float unpack_val(u64 k) {
    unsigned int u = (unsigned int)(k >> 32);
    u = (u & 0x80000000u) ? (u & 0x7FFFFFFFu) : ~u;
    return __uint_as_float(u);
}

__device__ __forceinline__ u64 u64min(u64 a, u64 b) { return a < b ? a : b; }
__device__ __forceinline__ u64 u64max(u64 a, u64 b) { return a > b ? a : b; }

// merge two u64-packed top-2 pairs
__device__ __forceinline__ void top2_merge(u64& k1, u64& k2, u64 j1, u64 j2) {
    u64 lo = u64min(k1, j1);
    u64 hi = u64max(k1, j1);
    k1 = lo;
    k2 = u64min(u64min(k2, j2), hi);
}

// fp32 top-2 push (cheap predicated form)
__device__ __forceinline__ void top2f_push(float& v1, unsigned& i1, float& v2, unsigned& i2,
                                           float d, unsigned n) {
    if (d < v1) { v2 = v1; i2 = i1; v1 = d; i1 = n; }
    else if (d < v2) { v2 = d; i2 = n; }
}

// ---------------- Prologue: e_sq ----------------

__global__ void vq_init_kernel(const float* __restrict__ embed) {
    int gtid = blockIdx.x * blockDim.x + threadIdx.x;
    int warp = gtid >> 5;
    int lane = gtid & 31;
    if (warp < N_CODES) {
        const float* e = embed + (size_t)warp * K_DIM;
        float s = 0.f;
        #pragma unroll
        for (int k = lane * 4; k < K_DIM; k += 128) {
            float4 v = *(const float4*)(e + k);
            s += v.x * v.x + v.y * v.y + v.z * v.z + v.w * v.w;
        }
        #pragma unroll
        for (int o = 16; o > 0; o >>= 1) s += __shfl_xor_sync(0xffffffffu, s, o);
        if (lane == 0) g_esq[warp] = s;
    }
}

// ---------------- Prologue: fp16 convert of x and embed ----------------

__global__ void vq_convert_kernel(const float* __restrict__ x, const float* __restrict__ embed) {
    const int gtid = blockIdx.x * blockDim.x + threadIdx.x;
    const int M4 = M_ROWS * K_DIM / 4;
    const int T4 = (M_ROWS + N_CODES) * K_DIM / 4;
    if (gtid >= T4) return;
    const float4* src;
    __half* dst;
    int q;
    if (gtid < M4) { q = gtid; src = (const float4*)x; dst = g_xh; }
    else { q = gtid - M4; src = (const float4*)embed; dst = g_eh; }
    float4 v = __ldg(&src[q]);
    ushort4 ua;
    unsigned short* pa = (unsigned short*)&ua;
    pa[0] = __half_as_ushort(__float2half_rn(v.x));
    pa[1] = __half_as_ushort(__float2half_rn(v.y));
    pa[2] = __half_as_ushort(__float2half_rn(v.z));
    pa[3] = __half_as_ushort(__float2half_rn(v.w));
    *(ushort4*)(&dst[(size_t)q * 4]) = ua;
}

// ---------------- Phase 1: fp16 screening GEMM (128x256) + per-CTA top-2 ----------------

__global__ __launch_bounds__(256) void vq_mma_kernel() {
    extern __shared__ char tiles[];
    __shared__ float esq_s[BN];
    __shared__ u64 red[2][BM][2];

    const int tid = threadIdx.x;
    const int wid = tid >> 5;
    const int lane = tid & 31;
    const int m0 = blockIdx.x * BM;
    const int n0 = blockIdx.y * BN;
    const int wm0 = (wid & 3) * 32;        // warp M origin (4 warps in M)
    const int whalf = wid >> 2;            // warp N half: 0 -> cols 0..127, 1 -> 128..255
    const int wn0 = whalf * 128;

    esq_s[tid] = g_esq[n0 + tid];          // BN == blockDim == 256

    const uint32_t tiles_base = smem_u32(tiles);

    // tile fill mapping: row = tid>>1 (0..127), 64-byte half = tid&1, SW128 swizzle
    const int lrow = tid >> 1;
    const int lhalf = tid & 1;
    uint32_t st_off[4];
    {
        const uint32_t off0 = (uint32_t)lrow * 128u + (uint32_t)lhalf * 64u;
        #pragma unroll
        for (int i = 0; i < 4; i++) {
            uint32_t o = off0 + i * 16u;
            st_off[i] = o ^ ((o >> 3) & 0x70u);
        }
    }
    const size_t a_off = (size_t)(m0 + lrow) * K_DIM + lhalf * 32;
    const size_t b_off0 = (size_t)(n0 + lrow) * K_DIM + lhalf * 32;
    const size_t b_off1 = (size_t)(n0 + 128 + lrow) * K_DIM + lhalf * 32;

    // ldmatrix addressing (K-major, non-trans)
    const int l15 = lane & 15;
    const int hi16 = (lane >> 4) * 16;
    uint32_t arow[2], arx[2], brow[8], brx[8];
    #pragma unroll
    for (int mi = 0; mi < 2; mi++) {
        int r = wm0 + mi * 16 + l15;
        arow[mi] = (uint32_t)r * 128u;
        arx[mi] = (uint32_t)(r & 7) * 16u;
    }
    #pragma unroll
    for (int g = 0; g < 8; g++) {
        int r = g * 16 + l15;              // local row within this warp's B half-tile
        brow[g] = (uint32_t)r * 128u;
        brx[g] = (uint32_t)(r & 7) * 16u;
    }

    float acc[2][16][4];
    #pragma unroll
    for (int mi = 0; mi < 2; mi++)
        #pragma unroll
        for (int nj = 0; nj < 16; nj++)
            #pragma unroll
            for (int q = 0; q < 4; q++) acc[mi][nj][q] = 0.f;

    // issue chunk-0 copies (A + Blo + Bhi)
    {
        uint32_t ta = tiles_base;
        uint32_t tb0 = tiles_base + TILE_BYTES;
        uint32_t tb1 = tiles_base + 2 * TILE_BYTES;
        #pragma unroll
        for (int i = 0; i < 4; i++) {
            cp16(ta + st_off[i], &g_xh[a_off] + i * 8);
            cp16(tb0 + st_off[i], &g_eh[b_off0] + i * 8);
            cp16(tb1 + st_off[i], &g_eh[b_off1] + i * 8);
        }
        cp_commit();
    }

    #pragma unroll 1
    for (int c = 0; c < NCHUNK; c++) {
        const int buf = c & 1;
        if (c + 1 < NCHUNK) {
            const int kofs = (c + 1) * KC;
            const int nb = buf ^ 1;
            uint32_t ta = tiles_base + (nb * 3) * TILE_BYTES;
            uint32_t tb0 = ta + TILE_BYTES;
            uint32_t tb1 = ta + 2 * TILE_BYTES;
            #pragma unroll
            for (int i = 0; i < 4; i++) {
                cp16(ta + st_off[i], &g_xh[a_off + kofs] + i * 8);
                cp16(tb0 + st_off[i], &g_eh[b_off0 + kofs] + i * 8);
                cp16(tb1 + st_off[i], &g_eh[b_off1 + kofs] + i * 8);
            }
            cp_commit();
            cp_wait<1>();     // chunk c resident, chunk c+1 in flight
        } else {
            cp_wait<0>();
        }
        __syncthreads();

        const uint32_t ta = tiles_base + (buf * 3) * TILE_BYTES;
        const uint32_t tb = tiles_base + (buf * 3 + 1 + whalf) * TILE_BYTES;
        #pragma unroll
        for (int ks = 0; ks < 4; ks++) {
            const uint32_t kc = (uint32_t)(ks * 32 + hi16);
            uint32_t a[2][4], b[8][4];
            #pragma unroll
            for (int mi = 0; mi < 2; mi++)
                ldsm4(a[mi][0], a[mi][1], a[mi][2], a[mi][3],
                      ta + arow[mi] + (kc ^ arx[mi]));
            #pragma unroll
            for (int g = 0; g < 8; g++)
                ldsm4(b[g][0], b[g][1], b[g][2], b[g][3],
                      tb + brow[g] + (kc ^ brx[g]));
            #pragma unroll
            for (int mi = 0; mi < 2; mi++)
                #pragma unroll
                for (int g = 0; g < 8; g++) {
                    mma16816(acc[mi][g * 2 + 0], a[mi], b[g][0], b[g][2]);
                    mma16816(acc[mi][g * 2 + 1], a[mi], b[g][1], b[g][3]);
                }
        }
        __syncthreads();   // all warps done reading buf before it is overwritten
    }

    // ---- epilogue: approx dist = e_sq[n] - 2*dot; fp32 top-2 per (row, CTA) ----
    const int cbase = wn0 + (lane & 3) * 2;
    #pragma unroll
    for (int mi = 0; mi < 2; mi++) {
        #pragma unroll
        for (int rh = 0; rh < 2; rh++) {
            float v1 = 3.4e38f, v2 = 3.4e38f;
            unsigned i1 = 0, i2 = 0;
            #pragma unroll
            for (int nj = 0; nj < 16; nj++) {
                const int nc = cbase + nj * 8;
                const float d0 = fmaf(-2.f, acc[mi][nj][rh * 2 + 0], esq_s[nc]);
                const float d1 = fmaf(-2.f, acc[mi][nj][rh * 2 + 1], esq_s[nc + 1]);
                top2f_push(v1, i1, v2, i2, d0, (unsigned)(n0 + nc));
                top2f_push(v1, i1, v2, i2, d1, (unsigned)(n0 + nc + 1));
            }
            u64 k1 = pack_key(v1, i1), k2 = pack_key(v2, i2);
            // merge across the lane quad (lanes sharing the same row)
            #pragma unroll
            for (int o = 1; o <= 2; o <<= 1) {
                u64 j1 = __shfl_xor_sync(0xffffffffu, k1, o);
                u64 j2 = __shfl_xor_sync(0xffffffffu, k2, o);
                top2_merge(k1, k2, j1, j2);
            }
            if ((lane & 3) == 0) {
                const int row = wm0 + mi * 16 + rh * 8 + (lane >> 2);
                red[whalf][row][0] = k1;
                red[whalf][row][1] = k2;
            }
        }
    }
    __syncthreads();
    if (tid < BM) {
        u64 k1 = red[0][tid][0], k2 = red[0][tid][1];
        top2_merge(k1, k2, red[1][tid][0], red[1][tid][1]);
        g_cand[m0 + tid][blockIdx.y][0] = k1;
        g_cand[m0 + tid][blockIdx.y][1] = k2;
    }
}

// ---------------- Phase 2: exact fp32 rescue + output write (one warp per row) ----------------

__global__ __launch_bounds__(256) void vq_refine_kernel(const float* __restrict__ x,
                                                        const float* __restrict__ embed,
                                                        float* __restrict__ out,
                                                        int write_idx) {
    const int row = blockIdx.x * 8 + (threadIdx.x >> 5);
    const int lane = threadIdx.x & 31;

    // x row into registers: 8 floats per lane
    const float4* xr = (const float4*)(x + (size_t)row * K_DIM);
    const float4 xa = __ldg(&xr[lane * 2]);
    const float4 xb = __ldg(&xr[lane * 2 + 1]);

    // this row's 64 candidate keys (2 per lane)
    const u64* cp = &g_cand[row][0][0];
    u64 keys[2];
    #pragma unroll
    for (int i = 0; i < 2; i++) keys[i] = cp[lane + 32 * i];

    // approx min over all candidates
    u64 kmin = u64min(keys[0], keys[1]);
    #pragma unroll
    for (int o = 16; o > 0; o >>= 1)
        kmin = u64min(kmin, __shfl_xor_sync(0xffffffffu, kmin, o));
    const float thresh = unpack_val(kmin) + MARGIN;

    u64 best = 0xFFFFFFFFFFFFFFFFull;
    #pragma unroll
    for (int i = 0; i < 2; i++) {
        unsigned mask = __ballot_sync(0xffffffffu, unpack_val(keys[i]) <= thresh);
        while (mask) {
            const int src = __ffs(mask) - 1;
            mask &= mask - 1;
            const unsigned idx = (unsigned)(__shfl_sync(0xffffffffu, keys[i], src) & 0xFFFFFFFFull);
            const float4* er = (const float4*)(embed + (size_t)idx * K_DIM);
            const float4 ea = __ldg(&er[lane * 2]);
            const float4 eb = __ldg(&er[lane * 2 + 1]);
            float s = xa.x * ea.x + xa.y * ea.y + xa.z * ea.z + xa.w * ea.w
                    + xb.x * eb.x + xb.y * eb.y + xb.z * eb.z + xb.w * eb.w;
            #pragma unroll
            for (int o = 16; o > 0; o >>= 1) s += __shfl_xor_sync(0xffffffffu, s, o);
            const float d = fmaf(-2.f, s, __ldg(&g_esq[idx]));
            best = u64min(best, pack_key(d, idx));
        }
    }

    // winner: gather codebook row directly into the output (gather kernel folded in)
    const unsigned widx = (unsigned)(__shfl_sync(0xffffffffu, best, 0) & 0xFFFFFFFFull);
    const float4* er = (const float4*)(embed + (size_t)widx * K_DIM);
    float4* orow = (float4*)(out + (size_t)row * K_DIM);
    orow[lane * 2] = __ldg(&er[lane * 2]);
    orow[lane * 2 + 1] = __ldg(&er[lane * 2 + 1]);
    if (write_idx && lane == 0)
        out[(size_t)M_ROWS * K_DIM + row] = (float)widx;
}

extern "C" void kernel_launch(void* const* d_in, const int* in_sizes, int n_in,
                              void* d_out, int out_size) {
    const float* x = (const float*)d_in[0];      // [8,1024,256] f32
    const float* embed = (const float*)d_in[1];  // [8192,256] f32
    float* out = (float*)d_out;

    cudaFuncSetAttribute(vq_mma_kernel, cudaFuncAttributeMaxDynamicSharedMemorySize, SMEM_DYN);

    vq_init_kernel<<<1024, 256>>>(embed);

    const int T4 = (M_ROWS + N_CODES) * K_DIM / 4;
    vq_convert_kernel<<<(T4 + 255) / 256, 256>>>(x, embed);

    dim3 grid(M_ROWS / BM, N_CODES / BN);
    vq_mma_kernel<<<grid, 256, SMEM_DYN>>>();

    const int write_idx = (out_size >= M_ROWS * K_DIM + M_ROWS) ? 1 : 0;
    vq_refine_kernel<<<M_ROWS / 8, 256>>>(x, embed, out, write_idx);
}

// round 12
// speedup vs baseline: 5.1457x; 1.2305x over previous
#include <cuda_runtime.h>
#include <cuda_fp16.h>
#include <stdint.h>

#define M_ROWS 8192
#define N_CODES 8192
#define K_DIM 256

#define BM 128
#define BN 128
#define NCTA_N (N_CODES / BN)        // 64
#define KC 64                        // fp16 K elems per chunk (128 B rows)
#define NCHUNK (K_DIM / KC)          // 4
#define TILE_BYTES (128 * 128)       // 128 rows x 128 bytes
#define SMEM_DYN (4 * TILE_BYTES)    // 2 stages x (1 A + 1 B) tiles = 64 KB
#define MARGIN 1.0f                  // covers fp16 screen error difference

typedef unsigned long long u64;

__device__ float g_esq[N_CODES];
__device__ u64 g_cand[M_ROWS][NCTA_N][2];      // top-2 approx candidates per (row, N-CTA)
__device__ __half g_xh[M_ROWS * K_DIM];
__device__ __half g_eh[N_CODES * K_DIM];

// ---------------- baseline-PTX helpers (valid on plain sm_103 target) ----------------

__device__ __forceinline__ uint32_t smem_u32(const void* p) {
    uint32_t a;
    asm("{ .reg .u64 t; cvta.to.shared.u64 t, %1; cvt.u32.u64 %0, t; }" : "=r"(a) : "l"(p));
    return a;
}

__device__ __forceinline__ void cp16(uint32_t dst, const void* src) {
    asm volatile("cp.async.cg.shared.global [%0], [%1], 16;" :: "r"(dst), "l"(src));
}
__device__ __forceinline__ void cp_commit() { asm volatile("cp.async.commit_group;" ::: "memory"); }
template <int N> __device__ __forceinline__ void cp_wait() {
    asm volatile("cp.async.wait_group %0;" :: "n"(N) : "memory");
}

__device__ __forceinline__ void ldsm4(uint32_t& r0, uint32_t& r1, uint32_t& r2, uint32_t& r3,
                                      uint32_t addr) {
    asm volatile("ldmatrix.sync.aligned.m8n8.x4.shared.b16 {%0,%1,%2,%3}, [%4];"
                 : "=r"(r0), "=r"(r1), "=r"(r2), "=r"(r3) : "r"(addr));
}

__device__ __forceinline__ void mma16816(float* d, const uint32_t* a, uint32_t b0, uint32_t b1) {
    asm volatile(
        "mma.sync.aligned.m16n8k16.row.col.f32.f16.f16.f32 "
        "{%0,%1,%2,%3}, {%4,%5,%6,%7}, {%8,%9}, {%0,%1,%2,%3};"
        : "+f"(d[0]), "+f"(d[1]), "+f"(d[2]), "+f"(d[3])
        : "r"(a[0]), "r"(a[1]), "r"(a[2]), "r"(a[3]), "r"(b0), "r"(b1));
}

__device__ __forceinline__ u64 pack_key(float v, unsigned int idx) {
    unsigned int u = __float_as_uint(v);
    u = (u & 0x80000000u) ? ~u : (u | 0x80000000u);
    return ((u64)u << 32) | (u64)idx;
}
__device__ __forceinline__ float unpack_val(u64 k) {
    unsigned int u = (unsigned int)(k >> 32);
    u = (u & 0x80000000u) ? (u & 0x7FFFFFFFu) : ~u;
    return __uint_as_float(u);
}

__device__ __forceinline__ u64 u64min(u64 a, u64 b) { return a < b ? a : b; }
__device__ __forceinline__ u64 u64max(u64 a, u64 b) { return a > b ? a : b; }

// merge two u64-packed top-2 pairs
__device__ __forceinline__ void top2_merge(u64& k1, u64& k2, u64 j1, u64 j2) {
    u64 lo = u64min(k1, j1);
    u64 hi = u64max(k1, j1);
    k1 = lo;
    k2 = u64min(u64min(k2, j2), hi);
}

// fp32 top-2 push (cheap predicated form)
__device__ __forceinline__ void top2f_push(float& v1, unsigned& i1, float& v2, unsigned& i2,
                                           float d, unsigned n) {
    if (d < v1) { v2 = v1; i2 = i1; v1 = d; i1 = n; }
    else if (d < v2) { v2 = d; i2 = n; }
}

// ---------------- Prologue: e_sq ----------------

__global__ void vq_init_kernel(const float* __restrict__ embed) {
    int gtid = blockIdx.x * blockDim.x + threadIdx.x;
    int warp = gtid >> 5;
    int lane = gtid & 31;
    if (warp < N_CODES) {
        const float* e = embed + (size_t)warp * K_DIM;
        float s = 0.f;
        #pragma unroll
        for (int k = lane * 4; k < K_DIM; k += 128) {
            float4 v = *(const float4*)(e + k);
            s += v.x * v.x + v.y * v.y + v.z * v.z + v.w * v.w;
        }
        #pragma unroll
        for (int o = 16; o > 0; o >>= 1) s += __shfl_xor_sync(0xffffffffu, s, o);
        if (lane == 0) g_esq[warp] = s;
    }
}

// ---------------- Prologue: fp16 convert of x and embed ----------------

__global__ void vq_convert_kernel(const float* __restrict__ x, const float* __restrict__ embed) {
    const int gtid = blockIdx.x * blockDim.x + threadIdx.x;
    const int M4 = M_ROWS * K_DIM / 4;
    const int T4 = (M_ROWS + N_CODES) * K_DIM / 4;
    if (gtid >= T4) return;
    const float4* src;
    __half* dst;
    int q;
    if (gtid < M4) { q = gtid; src = (const float4*)x; dst = g_xh; }
    else { q = gtid - M4; src = (const float4*)embed; dst = g_eh; }
    float4 v = __ldg(&src[q]);
    ushort4 ua;
    unsigned short* pa = (unsigned short*)&ua;
    pa[0] = __half_as_ushort(__float2half_rn(v.x));
    pa[1] = __half_as_ushort(__float2half_rn(v.y));
    pa[2] = __half_as_ushort(__float2half_rn(v.z));
    pa[3] = __half_as_ushort(__float2half_rn(v.w));
    *(ushort4*)(&dst[(size_t)q * 4]) = ua;
}

// ---------------- Phase 1: fp16 screening GEMM (128x128) + per-CTA top-2 ----------------

__global__ __launch_bounds__(256, 2) void vq_mma_kernel() {
    extern __shared__ char tiles[];
    __shared__ float esq_s[BN];
    __shared__ u64 red[2][BM][2];

    const int tid = threadIdx.x;
    const int wid = tid >> 5;
    const int lane = tid & 31;
    const int m0 = blockIdx.x * BM;
    const int n0 = blockIdx.y * BN;
    const int wm0 = (wid & 3) * 32;        // warp M origin (4 warps in M)
    const int wn0 = (wid >> 2) * 64;       // warp N origin (2 warps in N)

    if (tid < BN) esq_s[tid] = g_esq[n0 + tid];

    const uint32_t tiles_base = smem_u32(tiles);

    // tile fill mapping: row = tid>>1 (0..127), 64-byte half = tid&1, SW128 swizzle
    const int lrow = tid >> 1;
    const int lhalf = tid & 1;
    uint32_t st_off[4];
    {
        const uint32_t off0 = (uint32_t)lrow * 128u + (uint32_t)lhalf * 64u;
        #pragma unroll
        for (int i = 0; i < 4; i++) {
            uint32_t o = off0 + i * 16u;
            st_off[i] = o ^ ((o >> 3) & 0x70u);
        }
    }
    const size_t a_off = (size_t)(m0 + lrow) * K_DIM + lhalf * 32;
    const size_t b_off = (size_t)(n0 + lrow) * K_DIM + lhalf * 32;

    // ldmatrix addressing (A and B both K-major -> identical non-trans pattern)
    const int l15 = lane & 15;
    const int hi16 = (lane >> 4) * 16;
    uint32_t arow[2], arx[2], brow[4], brx[4];
    #pragma unroll
    for (int mi = 0; mi < 2; mi++) {
        int r = wm0 + mi * 16 + l15;
        arow[mi] = (uint32_t)r * 128u;
        arx[mi] = (uint32_t)(r & 7) * 16u;
    }
    #pragma unroll
    for (int g = 0; g < 4; g++) {
        int r = wn0 + g * 16 + l15;
        brow[g] = (uint32_t)r * 128u;
        brx[g] = (uint32_t)(r & 7) * 16u;
    }

    float acc[2][8][4];
    #pragma unroll
    for (int mi = 0; mi < 2; mi++)
        #pragma unroll
        for (int nj = 0; nj < 8; nj++)
            #pragma unroll
            for (int q = 0; q < 4; q++) acc[mi][nj][q] = 0.f;

    // issue chunk-0 copies
    {
        uint32_t ta = tiles_base;
        uint32_t tb = tiles_base + TILE_BYTES;
        #pragma unroll
        for (int i = 0; i < 4; i++) {
            cp16(ta + st_off[i], &g_xh[a_off] + i * 8);
            cp16(tb + st_off[i], &g_eh[b_off] + i * 8);
        }
        cp_commit();
    }

    #pragma unroll 1
    for (int c = 0; c < NCHUNK; c++) {
        const int buf = c & 1;
        if (c + 1 < NCHUNK) {
            const int kofs = (c + 1) * KC;
            const int nb = buf ^ 1;
            uint32_t ta = tiles_base + (nb * 2) * TILE_BYTES;
            uint32_t tb = ta + TILE_BYTES;
            #pragma unroll
            for (int i = 0; i < 4; i++) {
                cp16(ta + st_off[i], &g_xh[a_off + kofs] + i * 8);
                cp16(tb + st_off[i], &g_eh[b_off + kofs] + i * 8);
            }
            cp_commit();
            cp_wait<1>();     // chunk c resident, chunk c+1 in flight
        } else {
            cp_wait<0>();
        }
        __syncthreads();

        const uint32_t ta = tiles_base + (buf * 2) * TILE_BYTES;
        const uint32_t tb = tiles_base + (buf * 2 + 1) * TILE_BYTES;
        #pragma unroll
        for (int ks = 0; ks < 4; ks++) {
            const uint32_t kc = (uint32_t)(ks * 32 + hi16);
            uint32_t a[2][4], b[4][4];
            #pragma unroll
            for (int mi = 0; mi < 2; mi++)
                ldsm4(a[mi][0], a[mi][1], a[mi][2], a[mi][3],
                      ta + arow[mi] + (kc ^ arx[mi]));
            #pragma unroll
            for (int g = 0; g < 4; g++)
                ldsm4(b[g][0], b[g][1], b[g][2], b[g][3],
                      tb + brow[g] + (kc ^ brx[g]));
            #pragma unroll
            for (int mi = 0; mi < 2; mi++)
                #pragma unroll
                for (int g = 0; g < 4; g++) {
                    mma16816(acc[mi][g * 2 + 0], a[mi], b[g][0], b[g][2]);
                    mma16816(acc[mi][g * 2 + 1], a[mi], b[g][1], b[g][3]);
                }
        }
        __syncthreads();   // all warps done reading buf before it is overwritten
    }

    // ---- epilogue: approx dist = e_sq[n] - 2*dot; fp32 top-2 per (row, CTA) ----
    const int cbase = wn0 + (lane & 3) * 2;
    #pragma unroll
    for (int mi = 0; mi < 2; mi++) {
        #pragma unroll
        for (int rh = 0; rh < 2; rh++) {
            float v1 = 3.4e38f, v2 = 3.4e38f;
            unsigned i1 = 0, i2 = 0;
            #pragma unroll
            for (int nj = 0; nj < 8; nj++) {
                const int nc = cbase + nj * 8;
                const float d0 = fmaf(-2.f, acc[mi][nj][rh * 2 + 0], esq_s[nc]);
                const float d1 = fmaf(-2.f, acc[mi][nj][rh * 2 + 1], esq_s[nc + 1]);
                top2f_push(v1, i1, v2, i2, d0, (unsigned)(n0 + nc));
                top2f_push(v1, i1, v2, i2, d1, (unsigned)(n0 + nc + 1));
            }
            u64 k1 = pack_key(v1, i1), k2 = pack_key(v2, i2);
            // merge across the lane quad (lanes sharing the same row)
            #pragma unroll
            for (int o = 1; o <= 2; o <<= 1) {
                u64 j1 = __shfl_xor_sync(0xffffffffu, k1, o);
                u64 j2 = __shfl_xor_sync(0xffffffffu, k2, o);
                top2_merge(k1, k2, j1, j2);
            }
            if ((lane & 3) == 0) {
                const int row = wm0 + mi * 16 + rh * 8 + (lane >> 2);
                red[wid >> 2][row][0] = k1;
                red[wid >> 2][row][1] = k2;
            }
        }
    }
    __syncthreads();
    if (tid < BM) {
        u64 k1 = red[0][tid][0], k2 = red[0][tid][1];
        top2_merge(k1, k2, red[1][tid][0], red[1][tid][1]);
        g_cand[m0 + tid][blockIdx.y][0] = k1;
        g_cand[m0 + tid][blockIdx.y][1] = k2;
    }
}

// ---------------- Phase 2: exact fp32 rescue + output write (one warp per row) ----------------

__global__ __launch_bounds__(256) void vq_refine_kernel(const float* __restrict__ x,
                                                        const float* __restrict__ embed,
                                                        float* __restrict__ out,
                                                        int write_idx) {
    const int row = blockIdx.x * 8 + (threadIdx.x >> 5);
    const int lane = threadIdx.x & 31;

    // x row into registers: 8 floats per lane
    const float4* xr = (const float4*)(x + (size_t)row * K_DIM);
    const float4 xa = __ldg(&xr[lane * 2]);
    const float4 xb = __ldg(&xr[lane * 2 + 1]);

    // this row's 128 candidate keys (4 per lane)
    const u64* cp = &g_cand[row][0][0];
    u64 keys[4];
    #pragma unroll
    for (int i = 0; i < 4; i++) keys[i] = cp[lane + 32 * i];

    // approx min over all candidates
    u64 kmin = u64min(u64min(keys[0], keys[1]), u64min(keys[2], keys[3]));
    #pragma unroll
    for (int o = 16; o > 0; o >>= 1)
        kmin = u64min(kmin, __shfl_xor_sync(0xffffffffu, kmin, o));
    const float thresh = unpack_val(kmin) + MARGIN;

    u64 best = 0xFFFFFFFFFFFFFFFFull;
    #pragma unroll
    for (int i = 0; i < 4; i++) {
        unsigned mask = __ballot_sync(0xffffffffu, unpack_val(keys[i]) <= thresh);
        while (mask) {
            const int src = __ffs(mask) - 1;
            mask &= mask - 1;
            const unsigned idx = (unsigned)(__shfl_sync(0xffffffffu, keys[i], src) & 0xFFFFFFFFull);
            const float4* er = (const float4*)(embed + (size_t)idx * K_DIM);
            const float4 ea = __ldg(&er[lane * 2]);
            const float4 eb = __ldg(&er[lane * 2 + 1]);
            float s = xa.x * ea.x + xa.y * ea.y + xa.z * ea.z + xa.w * ea.w
                    + xb.x * eb.x + xb.y * eb.y + xb.z * eb.z + xb.w * eb.w;
            #pragma unroll
            for (int o = 16; o > 0; o >>= 1) s += __shfl_xor_sync(0xffffffffu, s, o);
            const float d = fmaf(-2.f, s, __ldg(&g_esq[idx]));
            best = u64min(best, pack_key(d, idx));
        }
    }

    // winner: gather codebook row directly into the output (gather kernel folded in)
    const unsigned widx = (unsigned)(__shfl_sync(0xffffffffu, best, 0) & 0xFFFFFFFFull);
    const float4* er = (const float4*)(embed + (size_t)widx * K_DIM);
    float4* orow = (float4*)(out + (size_t)row * K_DIM);
    orow[lane * 2] = __ldg(&er[lane * 2]);
    orow[lane * 2 + 1] = __ldg(&er[lane * 2 + 1]);
    if (write_idx && lane == 0)
        out[(size_t)M_ROWS * K_DIM + row] = (float)widx;
}

extern "C" void kernel_launch(void* const* d_in, const int* in_sizes, int n_in,
                              void* d_out, int out_size) {
    const float* x = (const float*)d_in[0];      // [8,1024,256] f32
    const float* embed = (const float*)d_in[1];  // [8192,256] f32
    float* out = (float*)d_out;

    cudaFuncSetAttribute(vq_mma_kernel, cudaFuncAttributeMaxDynamicSharedMemorySize, SMEM_DYN);

    vq_init_kernel<<<1024, 256>>>(embed);

    const int T4 = (M_ROWS + N_CODES) * K_DIM / 4;
    vq_convert_kernel<<<(T4 + 255) / 256, 256>>>(x, embed);

    dim3 grid(M_ROWS / BM, N_CODES / BN);
    vq_mma_kernel<<<grid, 256, SMEM_DYN>>>();

    const int write_idx = (out_size >= M_ROWS * K_DIM + M_ROWS) ? 1 : 0;
    vq_refine_kernel<<<M_ROWS / 8, 256>>>(x, embed, out, write_idx);
}

// round 13
// speedup vs baseline: 5.1589x; 1.0026x over previous
#include <cuda_runtime.h>
#include <cuda_fp16.h>
#include <stdint.h>

#define M_ROWS 8192
#define N_CODES 8192
#define K_DIM 256

#define BM 128
#define BN 128
#define NCTA_N (N_CODES / BN)        // 64
#define KC 64                        // fp16 K elems per chunk (128 B rows)
#define NCHUNK (K_DIM / KC)          // 4
#define NSTAGE 3
#define TILE_BYTES (128 * 128)       // 128 rows x 128 bytes
#define SMEM_DYN (NSTAGE * 2 * TILE_BYTES)   // 3 stages x (A + B) = 96 KB
#define MARGIN 1.0f                  // covers fp16 screen error difference

typedef unsigned long long u64;

__device__ float g_esq[N_CODES];
__device__ u64 g_cand[M_ROWS][NCTA_N][2];      // top-2 approx candidates per (row, N-CTA)
__device__ __half g_xh[M_ROWS * K_DIM];
__device__ __half g_eh[N_CODES * K_DIM];

// ---------------- baseline-PTX helpers (valid on plain sm_103 target) ----------------

__device__ __forceinline__ uint32_t smem_u32(const void* p) {
    uint32_t a;
    asm("{ .reg .u64 t; cvta.to.shared.u64 t, %1; cvt.u32.u64 %0, t; }" : "=r"(a) : "l"(p));
    return a;
}

__device__ __forceinline__ void cp16(uint32_t dst, const void* src) {
    asm volatile("cp.async.cg.shared.global [%0], [%1], 16;" :: "r"(dst), "l"(src));
}
__device__ __forceinline__ void cp_commit() { asm volatile("cp.async.commit_group;" ::: "memory"); }
template <int N> __device__ __forceinline__ void cp_wait() {
    asm volatile("cp.async.wait_group %0;" :: "n"(N) : "memory");
}

__device__ __forceinline__ void ldsm4(uint32_t& r0, uint32_t& r1, uint32_t& r2, uint32_t& r3,
                                      uint32_t addr) {
    asm volatile("ldmatrix.sync.aligned.m8n8.x4.shared.b16 {%0,%1,%2,%3}, [%4];"
                 : "=r"(r0), "=r"(r1), "=r"(r2), "=r"(r3) : "r"(addr));
}

__device__ __forceinline__ void mma16816(float* d, const uint32_t* a, uint32_t b0, uint32_t b1) {
    asm volatile(
        "mma.sync.aligned.m16n8k16.row.col.f32.f16.f16.f32 "
        "{%0,%1,%2,%3}, {%4,%5,%6,%7}, {%8,%9}, {%0,%1,%2,%3};"
        : "+f"(d[0]), "+f"(d[1]), "+f"(d[2]), "+f"(d[3])
        : "r"(a[0]), "r"(a[1]), "r"(a[2]), "r"(a[3]), "r"(b0), "r"(b1));
}

__device__ __forceinline__ u64 pack_key(float v, unsigned int idx) {
    unsigned int u = __float_as_uint(v);
    u = (u & 0x80000000u) ? ~u : (u | 0x80000000u);
    return ((u64)u << 32) | (u64)idx;
}
__device__ __forceinline__ float unpack_val(u64 k) {
    unsigned int u = (unsigned int)(k >> 32);
    u = (u & 0x80000000u) ? (u & 0x7FFFFFFFu) : ~u;
    return __uint_as_float(u);
}

__device__ __forceinline__ u64 u64min(u64 a, u64 b) { return a < b ? a : b; }
__device__ __forceinline__ u64 u64max(u64 a, u64 b) { return a > b ? a : b; }

// merge two u64-packed top-2 pairs
__device__ __forceinline__ void top2_merge(u64& k1, u64& k2, u64 j1, u64 j2) {
    u64 lo = u64min(k1, j1);
    u64 hi = u64max(k1, j1);
    k1 = lo;
    k2 = u64min(u64min(k2, j2), hi);
}

// fp32 top-2 push (cheap predicated form)
__device__ __forceinline__ void top2f_push(float& v1, unsigned& i1, float& v2, unsigned& i2,
                                           float d, unsigned n) {
    if (d < v1) { v2 = v1; i2 = i1; v1 = d; i1 = n; }
    else if (d < v2) { v2 = d; i2 = n; }
}

// ---------------- Prologue (fused): fp16 convert of x and embed + e_sq ----------------
// One warp per row. Lanes cover 8 contiguous floats each (2 float4 -> 1 uint4 of halves).

__global__ __launch_bounds__(256) void vq_prep_kernel(const float* __restrict__ x,
                                                      const float* __restrict__ embed) {
    const int row = blockIdx.x * 8 + (threadIdx.x >> 5);
    const int lane = threadIdx.x & 31;
    const bool is_x = row < M_ROWS;
    const float* src = is_x ? (x + (size_t)row * K_DIM)
                            : (embed + (size_t)(row - M_ROWS) * K_DIM);
    __half* dst = is_x ? (g_xh + (size_t)row * K_DIM)
                       : (g_eh + (size_t)(row - M_ROWS) * K_DIM);

    const float4 v0 = __ldg((const float4*)src + lane * 2);
    const float4 v1 = __ldg((const float4*)src + lane * 2 + 1);
    float f[8] = {v0.x, v0.y, v0.z, v0.w, v1.x, v1.y, v1.z, v1.w};

    unsigned short h[8];
    float s = 0.f;
    #pragma unroll
    for (int i = 0; i < 8; i++) {
        h[i] = __half_as_ushort(__float2half_rn(f[i]));
        s = fmaf(f[i], f[i], s);
    }
    *((uint4*)(dst + lane * 8)) = *(const uint4*)h;

    if (!is_x) {
        #pragma unroll
        for (int o = 16; o > 0; o >>= 1) s += __shfl_xor_sync(0xffffffffu, s, o);
        if (lane == 0) g_esq[row - M_ROWS] = s;
    }
}

// ---------------- Phase 1: fp16 screening GEMM (128x128) + per-CTA top-2 ----------------

__global__ __launch_bounds__(256, 2) void vq_mma_kernel() {
    extern __shared__ char tiles[];
    __shared__ float esq_s[BN];
    __shared__ u64 red[2][BM][2];

    const int tid = threadIdx.x;
    const int wid = tid >> 5;
    const int lane = tid & 31;
    const int m0 = blockIdx.x * BM;
    const int n0 = blockIdx.y * BN;
    const int wm0 = (wid & 3) * 32;        // warp M origin (4 warps in M)
    const int wn0 = (wid >> 2) * 64;       // warp N origin (2 warps in N)

    if (tid < BN) esq_s[tid] = g_esq[n0 + tid];

    const uint32_t tiles_base = smem_u32(tiles);

    // tile fill mapping: row = tid>>1 (0..127), 64-byte half = tid&1, SW128 swizzle
    const int lrow = tid >> 1;
    const int lhalf = tid & 1;
    uint32_t st_off[4];
    {
        const uint32_t off0 = (uint32_t)lrow * 128u + (uint32_t)lhalf * 64u;
        #pragma unroll
        for (int i = 0; i < 4; i++) {
            uint32_t o = off0 + i * 16u;
            st_off[i] = o ^ ((o >> 3) & 0x70u);
        }
    }
    const size_t a_off = (size_t)(m0 + lrow) * K_DIM + lhalf * 32;
    const size_t b_off = (size_t)(n0 + lrow) * K_DIM + lhalf * 32;

    // ldmatrix addressing (A and B both K-major -> identical non-trans pattern)
    const int l15 = lane & 15;
    const int hi16 = (lane >> 4) * 16;
    uint32_t arow[2], arx[2], brow[4], brx[4];
    #pragma unroll
    for (int mi = 0; mi < 2; mi++) {
        int r = wm0 + mi * 16 + l15;
        arow[mi] = (uint32_t)r * 128u;
        arx[mi] = (uint32_t)(r & 7) * 16u;
    }
    #pragma unroll
    for (int g = 0; g < 4; g++) {
        int r = wn0 + g * 16 + l15;
        brow[g] = (uint32_t)r * 128u;
        brx[g] = (uint32_t)(r & 7) * 16u;
    }

    float acc[2][8][4];
    #pragma unroll
    for (int mi = 0; mi < 2; mi++)
        #pragma unroll
        for (int nj = 0; nj < 8; nj++)
            #pragma unroll
            for (int q = 0; q < 4; q++) acc[mi][nj][q] = 0.f;

    // issue chunk 0 and chunk 1 copies (stages 0, 1)
    #pragma unroll
    for (int c0 = 0; c0 < 2; c0++) {
        uint32_t ta = tiles_base + (c0 * 2) * TILE_BYTES;
        uint32_t tb = ta + TILE_BYTES;
        const int kofs = c0 * KC;
        #pragma unroll
        for (int i = 0; i < 4; i++) {
            cp16(ta + st_off[i], &g_xh[a_off + kofs] + i * 8);
            cp16(tb + st_off[i], &g_eh[b_off + kofs] + i * 8);
        }
        cp_commit();
    }

    #pragma unroll 1
    for (int c = 0; c < NCHUNK; c++) {
        const int stage = c % NSTAGE;
        if (c + 2 < NCHUNK) {
            // stage (c+2)%NSTAGE was last read by chunk c-1; the __syncthreads at the
            // end of that chunk's compute makes this overwrite safe.
            const int ns = (c + 2) % NSTAGE;
            const int kofs = (c + 2) * KC;
            uint32_t ta = tiles_base + (ns * 2) * TILE_BYTES;
            uint32_t tb = ta + TILE_BYTES;
            #pragma unroll
            for (int i = 0; i < 4; i++) {
                cp16(ta + st_off[i], &g_xh[a_off + kofs] + i * 8);
                cp16(tb + st_off[i], &g_eh[b_off + kofs] + i * 8);
            }
            cp_commit();
            cp_wait<2>();     // chunk c resident; c+1, c+2 in flight
        } else if (c + 1 < NCHUNK) {
            cp_wait<1>();     // chunk c resident; c+1 in flight
        } else {
            cp_wait<0>();
        }
        __syncthreads();

        const uint32_t ta = tiles_base + (stage * 2) * TILE_BYTES;
        const uint32_t tb = ta + TILE_BYTES;
        #pragma unroll
        for (int ks = 0; ks < 4; ks++) {
            const uint32_t kc = (uint32_t)(ks * 32 + hi16);
            uint32_t a[2][4], b[4][4];
            #pragma unroll
            for (int mi = 0; mi < 2; mi++)
                ldsm4(a[mi][0], a[mi][1], a[mi][2], a[mi][3],
                      ta + arow[mi] + (kc ^ arx[mi]));
            #pragma unroll
            for (int g = 0; g < 4; g++)
                ldsm4(b[g][0], b[g][1], b[g][2], b[g][3],
                      tb + brow[g] + (kc ^ brx[g]));
            #pragma unroll
            for (int mi = 0; mi < 2; mi++)
                #pragma unroll
                for (int g = 0; g < 4; g++) {
                    mma16816(acc[mi][g * 2 + 0], a[mi], b[g][0], b[g][2]);
                    mma16816(acc[mi][g * 2 + 1], a[mi], b[g][1], b[g][3]);
                }
        }
        __syncthreads();   // all warps done reading this stage before it is refilled
    }

    // ---- epilogue: approx dist = e_sq[n] - 2*dot; fp32 top-2 per (row, CTA) ----
    const int cbase = wn0 + (lane & 3) * 2;
    #pragma unroll
    for (int mi = 0; mi < 2; mi++) {
        #pragma unroll
        for (int rh = 0; rh < 2; rh++) {
            float v1 = 3.4e38f, v2 = 3.4e38f;
            unsigned i1 = 0, i2 = 0;
            #pragma unroll
            for (int nj = 0; nj < 8; nj++) {
                const int nc = cbase + nj * 8;
                const float d0 = fmaf(-2.f, acc[mi][nj][rh * 2 + 0], esq_s[nc]);
                const float d1 = fmaf(-2.f, acc[mi][nj][rh * 2 + 1], esq_s[nc + 1]);
                top2f_push(v1, i1, v2, i2, d0, (unsigned)(n0 + nc));
                top2f_push(v1, i1, v2, i2, d1, (unsigned)(n0 + nc + 1));
            }
            u64 k1 = pack_key(v1, i1), k2 = pack_key(v2, i2);
            // merge across the lane quad (lanes sharing the same row)
            #pragma unroll
            for (int o = 1; o <= 2; o <<= 1) {
                u64 j1 = __shfl_xor_sync(0xffffffffu, k1, o);
                u64 j2 = __shfl_xor_sync(0xffffffffu, k2, o);
                top2_merge(k1, k2, j1, j2);
            }
            if ((lane & 3) == 0) {
                const int row = wm0 + mi * 16 + rh * 8 + (lane >> 2);
                red[wid >> 2][row][0] = k1;
                red[wid >> 2][row][1] = k2;
            }
        }
    }
    __syncthreads();
    if (tid < BM) {
        u64 k1 = red[0][tid][0], k2 = red[0][tid][1];
        top2_merge(k1, k2, red[1][tid][0], red[1][tid][1]);
        g_cand[m0 + tid][blockIdx.y][0] = k1;
        g_cand[m0 + tid][blockIdx.y][1] = k2;
    }
}

// ---------------- Phase 2: exact fp32 rescue + output write (one warp per row) ----------------

__global__ __launch_bounds__(256) void vq_refine_kernel(const float* __restrict__ x,
                                                        const float* __restrict__ embed,
                                                        float* __restrict__ out,
                                                        int write_idx) {
    const int row = blockIdx.x * 8 + (threadIdx.x >> 5);
    const int lane = threadIdx.x & 31;

    // x row into registers: 8 floats per lane
    const float4* xr = (const float4*)(x + (size_t)row * K_DIM);
    const float4 xa = __ldg(&xr[lane * 2]);
    const float4 xb = __ldg(&xr[lane * 2 + 1]);

    // this row's 128 candidate keys (4 per lane)
    const u64* cp = &g_cand[row][0][0];
    u64 keys[4];
    #pragma unroll
    for (int i = 0; i < 4; i++) keys[i] = cp[lane + 32 * i];

    // approx min over all candidates
    u64 kmin = u64min(u64min(keys[0], keys[1]), u64min(keys[2], keys[3]));
    #pragma unroll
    for (int o = 16; o > 0; o >>= 1)
        kmin = u64min(kmin, __shfl_xor_sync(0xffffffffu, kmin, o));
    const float thresh = unpack_val(kmin) + MARGIN;

    u64 best = 0xFFFFFFFFFFFFFFFFull;
    #pragma unroll
    for (int i = 0; i < 4; i++) {
        unsigned mask = __ballot_sync(0xffffffffu, unpack_val(keys[i]) <= thresh);
        while (mask) {
            const int src = __ffs(mask) - 1;
            mask &= mask - 1;
            const unsigned idx = (unsigned)(__shfl_sync(0xffffffffu, keys[i], src) & 0xFFFFFFFFull);
            const float4* er = (const float4*)(embed + (size_t)idx * K_DIM);
            const float4 ea = __ldg(&er[lane * 2]);
            const float4 eb = __ldg(&er[lane * 2 + 1]);
            float s = xa.x * ea.x + xa.y * ea.y + xa.z * ea.z + xa.w * ea.w
                    + xb.x * eb.x + xb.y * eb.y + xb.z * eb.z + xb.w * eb.w;
            #pragma unroll
            for (int o = 16; o > 0; o >>= 1) s += __shfl_xor_sync(0xffffffffu, s, o);
            const float d = fmaf(-2.f, s, __ldg(&g_esq[idx]));
            best = u64min(best, pack_key(d, idx));
        }
    }

    // winner: gather codebook row directly into the output (gather kernel folded in)
    const unsigned widx = (unsigned)(__shfl_sync(0xffffffffu, best, 0) & 0xFFFFFFFFull);
    const float4* er = (const float4*)(embed + (size_t)widx * K_DIM);
    float4* orow = (float4*)(out + (size_t)row * K_DIM);
    orow[lane * 2] = __ldg(&er[lane * 2]);
    orow[lane * 2 + 1] = __ldg(&er[lane * 2 + 1]);
    if (write_idx && lane == 0)
        out[(size_t)M_ROWS * K_DIM + row] = (float)widx;
}

extern "C" void kernel_launch(void* const* d_in, const int* in_sizes, int n_in,
                              void* d_out, int out_size) {
    const float* x = (const float*)d_in[0];      // [8,1024,256] f32
    const float* embed = (const float*)d_in[1];  // [8192,256] f32
    float* out = (float*)d_out;

    cudaFuncSetAttribute(vq_mma_kernel, cudaFuncAttributeMaxDynamicSharedMemorySize, SMEM_DYN);

    vq_prep_kernel<<<(M_ROWS + N_CODES) / 8, 256>>>(x, embed);

    dim3 grid(M_ROWS / BM, N_CODES / BN);
    vq_mma_kernel<<<grid, 256, SMEM_DYN>>>();

    const int write_idx = (out_size >= M_ROWS * K_DIM + M_ROWS) ? 1 : 0;
    vq_refine_kernel<<<M_ROWS / 8, 256>>>(x, embed, out, write_idx);
}